// round 10
// baseline (speedup 1.0000x reference)
#include <cuda_runtime.h>
#include <math.h>
#include <stdint.h>

#define T_SEQ   2048
#define BATCH   2
#define DMODEL  1024
#define NHEADS  16
#define DHEAD   64
#define MROWS   (BATCH * T_SEQ)   // 4096
#define PI_F    3.14159265358979323846f

typedef unsigned long long u64;

// ---------------- device scratch (no allocations allowed) ----------------
__device__ float g_q [MROWS * DMODEL];
__device__ float g_k [MROWS * DMODEL];
__device__ float g_v [MROWS * DMODEL];
__device__ float g_ao[MROWS * DMODEL];

// ---------------- packed f32x2 helpers (plain sm_100+ PTX, no 'a') -------
__device__ __forceinline__ void fma2(u64 &d, u64 a, u64 b) {
    asm("fma.rn.f32x2 %0, %1, %2, %0;" : "+l"(d) : "l"(a), "l"(b));
}
__device__ __forceinline__ u64 mul2(u64 a, u64 b) {
    u64 r; asm("mul.rn.f32x2 %0, %1, %2;" : "=l"(r) : "l"(a), "l"(b)); return r;
}
__device__ __forceinline__ u64 dup2(float x) {
    u64 r; unsigned u = __float_as_uint(x);
    asm("mov.b64 %0, {%1, %2};" : "=l"(r) : "r"(u), "r"(u)); return r;
}
__device__ __forceinline__ float2 unpk2(u64 v) {
    unsigned lo, hi;
    asm("mov.b64 {%0, %1}, %2;" : "=r"(lo), "=r"(hi) : "l"(v));
    return make_float2(__uint_as_float(lo), __uint_as_float(hi));
}

// =========================================================================
// FFMA2 SGEMM (NT): C[m,n] = sum_k A[m,k] * B[n,k]
// 128x128 tile, BK=16, 256 threads, 8x8 microtile, packed-pair accumulators.
// B staged DUPLICATED in smem so dup-operands come straight from LDS.128.
// grid.z selects among up to 3 (B, C) pairs (fused Q/K/V projections).
// =========================================================================
__global__ __launch_bounds__(256)
void gemm_f2(const float* __restrict__ A,
             const float* __restrict__ W0, const float* __restrict__ W1,
             const float* __restrict__ W2,
             float* __restrict__ C0, float* __restrict__ C1,
             float* __restrict__ C2)
{
    __shared__ __align__(16) float As[16][132];   // [k][m] transposed
    __shared__ __align__(16) float Bs[16][264];   // [k][2n] duplicated

    const float* B = (blockIdx.z == 0) ? W0 : (blockIdx.z == 1) ? W1 : W2;
    float*       C = (blockIdx.z == 0) ? C0 : (blockIdx.z == 1) ? C1 : C2;

    const int tid = threadIdx.x;
    const int tx  = tid & 15;
    const int ty  = tid >> 4;
    const int r0  = ty << 3;              // 8 output rows
    const int c0  = tx << 3;              // 8 output cols
    const int bm  = blockIdx.y << 7;
    const int bn  = blockIdx.x << 7;

    const int row0 = tid >> 2;            // 0..63 (staging row; +64 2nd pass)
    const int kq   = (tid & 3) << 2;      // k quad

    u64 acc[4][8];                        // 4 row-pairs x 8 cols
#pragma unroll
    for (int i = 0; i < 4; i++)
#pragma unroll
        for (int j = 0; j < 8; j++) acc[i][j] = 0ull;

    const float* pA = A + (size_t)(bm + row0) * DMODEL + kq;
    const float* pB = B + (size_t)(bn + row0) * DMODEL + kq;

    float4 a0 = *(const float4*)pA;
    float4 a1 = *(const float4*)(pA + 64 * DMODEL);
    float4 b0 = *(const float4*)pB;
    float4 b1 = *(const float4*)(pB + 64 * DMODEL);

    for (int c = 0; c < 64; c++) {
        __syncthreads();                  // previous compute done with smem
        As[kq + 0][row0] = a0.x; As[kq + 1][row0] = a0.y;
        As[kq + 2][row0] = a0.z; As[kq + 3][row0] = a0.w;
        As[kq + 0][row0 + 64] = a1.x; As[kq + 1][row0 + 64] = a1.y;
        As[kq + 2][row0 + 64] = a1.z; As[kq + 3][row0 + 64] = a1.w;

        *(float2*)&Bs[kq + 0][2 * row0] = make_float2(b0.x, b0.x);
        *(float2*)&Bs[kq + 1][2 * row0] = make_float2(b0.y, b0.y);
        *(float2*)&Bs[kq + 2][2 * row0] = make_float2(b0.z, b0.z);
        *(float2*)&Bs[kq + 3][2 * row0] = make_float2(b0.w, b0.w);
        *(float2*)&Bs[kq + 0][2 * (row0 + 64)] = make_float2(b1.x, b1.x);
        *(float2*)&Bs[kq + 1][2 * (row0 + 64)] = make_float2(b1.y, b1.y);
        *(float2*)&Bs[kq + 2][2 * (row0 + 64)] = make_float2(b1.z, b1.z);
        *(float2*)&Bs[kq + 3][2 * (row0 + 64)] = make_float2(b1.w, b1.w);

        if (c < 63) {                     // prefetch next chunk (overlaps compute)
            pA += 16; pB += 16;
            a0 = *(const float4*)pA;
            a1 = *(const float4*)(pA + 64 * DMODEL);
            b0 = *(const float4*)pB;
            b1 = *(const float4*)(pB + 64 * DMODEL);
        }
        __syncthreads();

#pragma unroll
        for (int k = 0; k < 16; k++) {
            ulonglong2 aA = *(const ulonglong2*)&As[k][r0];
            ulonglong2 aB = *(const ulonglong2*)&As[k][r0 + 4];
            u64 ap[4] = {aA.x, aA.y, aB.x, aB.y};
            ulonglong2 d0 = *(const ulonglong2*)&Bs[k][2 * c0];
            ulonglong2 d1 = *(const ulonglong2*)&Bs[k][2 * c0 + 4];
            ulonglong2 d2 = *(const ulonglong2*)&Bs[k][2 * c0 + 8];
            ulonglong2 d3 = *(const ulonglong2*)&Bs[k][2 * c0 + 12];
            u64 bd[8] = {d0.x, d0.y, d1.x, d1.y, d2.x, d2.y, d3.x, d3.y};
#pragma unroll
            for (int i = 0; i < 4; i++)
#pragma unroll
                for (int j = 0; j < 8; j++)
                    fma2(acc[i][j], ap[i], bd[j]);
        }
    }

#pragma unroll
    for (int ip = 0; ip < 4; ip++) {
        float lo[8], hi[8];
#pragma unroll
        for (int j = 0; j < 8; j++) {
            float2 t = unpk2(acc[ip][j]);
            lo[j] = t.x; hi[j] = t.y;
        }
        float* cr0 = C + (size_t)(bm + r0 + 2 * ip) * DMODEL + bn + c0;
        float* cr1 = cr0 + DMODEL;
        *(float4*)(cr0)     = make_float4(lo[0], lo[1], lo[2], lo[3]);
        *(float4*)(cr0 + 4) = make_float4(lo[4], lo[5], lo[6], lo[7]);
        *(float4*)(cr1)     = make_float4(hi[0], hi[1], hi[2], hi[3]);
        *(float4*)(cr1 + 4) = make_float4(hi[4], hi[5], hi[6], hi[7]);
    }
}

// =========================================================================
// FFMA2 flash attention + rotation/valve epilogue.
// 64 queries x 128-key tiles, 256 threads.
//   S fragment: 4 rows x 8 cols (4 col-pairs), Q staged duplicated+scaled.
//   P stored duplicated [q][2*key] -> PV reads dup pairs via LDS.128.
//   O fragment: 4 rows x 4 cols (2 col-pairs), V pairs native.
// =========================================================================
#define SM_QD 0                       // Qd [64][132]  (dup q, scaled)
#define SM_KS 8448                    // Ks [64][132]  (d-major keys)
#define SM_VS 16896                   // Vs [128][68]
#define SM_SD 25600                   // Sd [64][264]  (dup P)
#define ATTN_SMEM ((25600 + 64 * 264) * 4)   // 169,984 B

__global__ __launch_bounds__(256)
void attn_f2(const float* __restrict__ Q, const float* __restrict__ Kg,
             const float* __restrict__ Vg,
             const float* __restrict__ beta_, const float* __restrict__ inval,
             const float* __restrict__ outval, const float* __restrict__ chiv,
             float* __restrict__ out)
{
    extern __shared__ __align__(16) float sm[];
    float* Qd = sm + SM_QD;
    float* Ks = sm + SM_KS;
    float* Vs = sm + SM_VS;
    float* Sd = sm + SM_SD;

    const int h   = blockIdx.y;
    const int b   = blockIdx.z;
    const int q0  = blockIdx.x << 6;
    const int tid = threadIdx.x;
    const int tx  = tid & 15;
    const int ty  = tid >> 4;
    const int r0  = ty << 2;          // 4 query rows
    const int c0  = tx << 3;          // 8 key cols (S)
    const int c0o = tx << 2;          // 4 dh cols (O)

    const float* qb = Q  + ((size_t)(b * T_SEQ + q0)) * DMODEL + h * DHEAD;
    const float* kb = Kg + ((size_t)(b * T_SEQ))      * DMODEL + h * DHEAD;
    const float* vb = Vg + ((size_t)(b * T_SEQ))      * DMODEL + h * DHEAD;

    // ---- stage Q duplicated + pre-scaled by 1/sqrt(dh) = 0.125 ----
#pragma unroll
    for (int i = 0; i < 4; i++) {
        int f  = tid + (i << 8);
        int q  = f >> 4;              // 0..63
        int dq = (f & 15) << 2;
        float4 v = *(const float4*)(qb + (size_t)q * DMODEL + dq);
        *(float2*)&Qd[(dq + 0) * 132 + 2 * q] = make_float2(v.x * 0.125f, v.x * 0.125f);
        *(float2*)&Qd[(dq + 1) * 132 + 2 * q] = make_float2(v.y * 0.125f, v.y * 0.125f);
        *(float2*)&Qd[(dq + 2) * 132 + 2 * q] = make_float2(v.z * 0.125f, v.z * 0.125f);
        *(float2*)&Qd[(dq + 3) * 132 + 2 * q] = make_float2(v.w * 0.125f, v.w * 0.125f);
    }

    float m_i[4] = {-1e30f, -1e30f, -1e30f, -1e30f};
    float l_i[4] = {0.f, 0.f, 0.f, 0.f};
    u64 o2[4][2];
#pragma unroll
    for (int i = 0; i < 4; i++) { o2[i][0] = 0ull; o2[i][1] = 0ull; }

    for (int kt = 0; kt < T_SEQ / 128; kt++) {
        __syncthreads();              // prior tile's reads of Ks/Vs done
        const float* kbt = kb + (size_t)kt * 128 * DMODEL;
        const float* vbt = vb + (size_t)kt * 128 * DMODEL;
#pragma unroll
        for (int i = 0; i < 8; i++) {
            int f   = tid + (i << 8);
            int key = f >> 4;         // 0..127
            int dq  = (f & 15) << 2;
            float4 kv = *(const float4*)(kbt + (size_t)key * DMODEL + dq);
            Ks[(dq + 0) * 132 + key] = kv.x;
            Ks[(dq + 1) * 132 + key] = kv.y;
            Ks[(dq + 2) * 132 + key] = kv.z;
            Ks[(dq + 3) * 132 + key] = kv.w;
            float4 vv = *(const float4*)(vbt + (size_t)key * DMODEL + dq);
            *(float4*)&Vs[key * 68 + dq] = vv;
        }
        __syncthreads();

        // ---- S = (Q/8) K^T : 4x8 fragment as 4x4 col-pairs ----
        u64 s2[4][4];
#pragma unroll
        for (int i = 0; i < 4; i++)
#pragma unroll
            for (int jp = 0; jp < 4; jp++) s2[i][jp] = 0ull;

#pragma unroll 4
        for (int d = 0; d < 64; d++) {
            ulonglong2 qa = *(const ulonglong2*)&Qd[d * 132 + 2 * r0];
            ulonglong2 qbp = *(const ulonglong2*)&Qd[d * 132 + 2 * r0 + 4];
            ulonglong2 ka = *(const ulonglong2*)&Ks[d * 132 + c0];
            ulonglong2 kbp2 = *(const ulonglong2*)&Ks[d * 132 + c0 + 4];
            u64 qd_[4] = {qa.x, qa.y, qbp.x, qbp.y};
            u64 kp_[4] = {ka.x, ka.y, kbp2.x, kbp2.y};
#pragma unroll
            for (int i = 0; i < 4; i++)
#pragma unroll
                for (int jp = 0; jp < 4; jp++)
                    fma2(s2[i][jp], qd_[i], kp_[jp]);
        }

        // ---- online softmax (row groups = 16-lane half-warps) ----
#pragma unroll
        for (int i = 0; i < 4; i++) {
            float2 e0 = unpk2(s2[i][0]);
            float2 e1 = unpk2(s2[i][1]);
            float2 e2 = unpk2(s2[i][2]);
            float2 e3 = unpk2(s2[i][3]);
            float s0 = e0.x, s1 = e0.y, s2a = e1.x, s3 = e1.y;
            float s4 = e2.x, s5 = e2.y, s6 = e3.x, s7 = e3.y;
            float mx = fmaxf(fmaxf(fmaxf(s0, s1), fmaxf(s2a, s3)),
                             fmaxf(fmaxf(s4, s5), fmaxf(s6, s7)));
#pragma unroll
            for (int off = 8; off > 0; off >>= 1)
                mx = fmaxf(mx, __shfl_xor_sync(0xffffffffu, mx, off));
            float nm = fmaxf(m_i[i], mx);
            float al = __expf(m_i[i] - nm);
            float p0 = __expf(s0 - nm), p1 = __expf(s1 - nm);
            float p2 = __expf(s2a - nm), p3 = __expf(s3 - nm);
            float p4 = __expf(s4 - nm), p5 = __expf(s5 - nm);
            float p6 = __expf(s6 - nm), p7 = __expf(s7 - nm);
            float ps = ((p0 + p1) + (p2 + p3)) + ((p4 + p5) + (p6 + p7));
#pragma unroll
            for (int off = 8; off > 0; off >>= 1)
                ps += __shfl_xor_sync(0xffffffffu, ps, off);
            l_i[i] = l_i[i] * al + ps;
            m_i[i] = nm;
            u64 a2 = dup2(al);
            o2[i][0] = mul2(o2[i][0], a2);
            o2[i][1] = mul2(o2[i][1], a2);
            // store P duplicated: Sd[q][2*key]
            float* sr = Sd + (r0 + i) * 264 + 2 * c0;
            *(float2*)(sr +  0) = make_float2(p0, p0);
            *(float2*)(sr +  2) = make_float2(p1, p1);
            *(float2*)(sr +  4) = make_float2(p2, p2);
            *(float2*)(sr +  6) = make_float2(p3, p3);
            *(float2*)(sr +  8) = make_float2(p4, p4);
            *(float2*)(sr + 10) = make_float2(p5, p5);
            *(float2*)(sr + 12) = make_float2(p6, p6);
            *(float2*)(sr + 14) = make_float2(p7, p7);
        }
        __syncwarp();     // P producer/consumer are the same half-warp

        // ---- O += P V ----
#pragma unroll 2
        for (int kk = 0; kk < 128; kk += 2) {
            u64 pd0[4], pd1[4];
#pragma unroll
            for (int i = 0; i < 4; i++) {
                ulonglong2 t = *(const ulonglong2*)&Sd[(r0 + i) * 264 + 2 * kk];
                pd0[i] = t.x; pd1[i] = t.y;
            }
            ulonglong2 v0 = *(const ulonglong2*)&Vs[kk * 68 + c0o];
            ulonglong2 v1 = *(const ulonglong2*)&Vs[(kk + 1) * 68 + c0o];
#pragma unroll
            for (int i = 0; i < 4; i++) {
                fma2(o2[i][0], pd0[i], v0.x);
                fma2(o2[i][1], pd0[i], v0.y);
                fma2(o2[i][0], pd1[i], v1.x);
                fma2(o2[i][1], pd1[i], v1.y);
            }
        }
        __syncwarp();     // PV reads of Sd done before next-tile overwrite
    }
    __syncthreads();      // all reads of Qd done -> reuse as O staging

    // ---- per-head constants ----
    float bsig = 1.f / (1.f + expf(-beta_[h]));
    float sa, ca;
    sincosf(PI_F * bsig, &sa, &ca);
    float iv  = 1.f / (1.f + expf(-inval[h]));
    float ov  = 1.f / (1.f + expf(-outval[h]));
    float gch = tanhf(chiv[h]);
    float fac = iv * ov * gch;        // rotation is linear: fold into one factor

    // stage normalized O into Qd region: Os[row][col], stride 68
#pragma unroll
    for (int i = 0; i < 4; i++) {
        float inv = 1.f / l_i[i];
        float2 u0 = unpk2(o2[i][0]);
        float2 u1 = unpk2(o2[i][1]);
        float* orow = Qd + (r0 + i) * 68 + c0o;
        orow[0] = u0.x * inv; orow[1] = u0.y * inv;
        orow[2] = u1.x * inv; orow[3] = u1.y * inv;
    }
    __syncthreads();

    // rotate halves (j, j+32), write [B,T,D] combined layout
    float* ob = out + ((size_t)(b * T_SEQ + q0)) * DMODEL + h * DHEAD;
#pragma unroll
    for (int it = 0; it < 8; it++) {
        int p = tid + (it << 8);
        int r = p >> 5;
        int j = p & 31;
        float xr = Qd[r * 68 + j];
        float xi = Qd[r * 68 + j + 32];
        ob[(size_t)r * DMODEL + j]      = (xr * ca - xi * sa) * fac;
        ob[(size_t)r * DMODEL + j + 32] = (xr * sa + xi * ca) * fac;
    }
}

// =========================================================================
extern "C" void kernel_launch(void* const* d_in, const int* in_sizes, int n_in,
                              void* d_out, int out_size)
{
    (void)in_sizes; (void)n_in; (void)out_size;

    const float* x    = (const float*)d_in[0];
    const float* Wq   = (const float*)d_in[1];
    const float* Wk   = (const float*)d_in[2];
    const float* Wv   = (const float*)d_in[3];
    const float* We   = (const float*)d_in[4];
    const float* beta = (const float*)d_in[5];
    const float* ivv  = (const float*)d_in[6];
    const float* ovv  = (const float*)d_in[7];
    const float* chi  = (const float*)d_in[8];
    float* out = (float*)d_out;

    float *qp, *kp, *vp, *ap;
    cudaGetSymbolAddress((void**)&qp, g_q);
    cudaGetSymbolAddress((void**)&kp, g_k);
    cudaGetSymbolAddress((void**)&vp, g_v);
    cudaGetSymbolAddress((void**)&ap, g_ao);

    cudaFuncSetAttribute(attn_f2, cudaFuncAttributeMaxDynamicSharedMemorySize,
                         (int)ATTN_SMEM);

    dim3 gqkv(DMODEL / 128, MROWS / 128, 3);   // (8, 32, 3) fused Q/K/V
    gemm_f2<<<gqkv, 256>>>(x, Wq, Wk, Wv, qp, kp, vp);

    dim3 ga(T_SEQ / 64, NHEADS, BATCH);        // (32, 16, 2)
    attn_f2<<<ga, 256, ATTN_SMEM>>>(qp, kp, vp, beta, ivv, ovv, chi, ap);

    dim3 go(DMODEL / 128, MROWS / 128, 1);     // (8, 32, 1) output proj
    gemm_f2<<<go, 256>>>(ap, We, We, We, out, out, out);
}

// round 11
// speedup vs baseline: 1.0012x; 1.0012x over previous
#include <cuda_runtime.h>
#include <math.h>
#include <stdint.h>

#define T_SEQ   2048
#define BATCH   2
#define DMODEL  1024
#define NHEADS  16
#define DHEAD   64
#define MROWS   (BATCH * T_SEQ)   // 4096
#define PI_F    3.14159265358979323846f

typedef unsigned long long u64;

// ---------------- device scratch (no allocations allowed) ----------------
__device__ float g_q [MROWS * DMODEL];
__device__ float g_k [MROWS * DMODEL];
__device__ float g_v [MROWS * DMODEL];
__device__ float g_ao[MROWS * DMODEL];

// ---------------- packed f32x2 helpers (plain sm_100+ PTX, no 'a') -------
__device__ __forceinline__ void fma2(u64 &d, u64 a, u64 b) {
    asm("fma.rn.f32x2 %0, %1, %2, %0;" : "+l"(d) : "l"(a), "l"(b));
}
__device__ __forceinline__ u64 mul2(u64 a, u64 b) {
    u64 r; asm("mul.rn.f32x2 %0, %1, %2;" : "=l"(r) : "l"(a), "l"(b)); return r;
}
__device__ __forceinline__ u64 dup2(float x) {
    u64 r; unsigned u = __float_as_uint(x);
    asm("mov.b64 %0, {%1, %2};" : "=l"(r) : "r"(u), "r"(u)); return r;
}
__device__ __forceinline__ float2 unpk2(u64 v) {
    unsigned lo, hi;
    asm("mov.b64 {%0, %1}, %2;" : "=r"(lo), "=r"(hi) : "l"(v));
    return make_float2(__uint_as_float(lo), __uint_as_float(hi));
}

// =========================================================================
// FFMA2 SGEMM (NT): C[m,n] = sum_k A[m,k] * B[n,k]
// 128x128 tile, BK=16, 256 threads, 8x8 microtile, packed-pair accumulators.
// B staged DUPLICATED in smem so dup-operands come straight from LDS.128.
// grid.z selects among up to 3 (B, C) pairs (fused Q/K/V projections).
// =========================================================================
__global__ __launch_bounds__(256)
void gemm_f2(const float* __restrict__ A,
             const float* __restrict__ W0, const float* __restrict__ W1,
             const float* __restrict__ W2,
             float* __restrict__ C0, float* __restrict__ C1,
             float* __restrict__ C2)
{
    __shared__ __align__(16) float As[16][132];   // [k][m] transposed
    __shared__ __align__(16) float Bs[16][264];   // [k][2n] duplicated

    const float* B = (blockIdx.z == 0) ? W0 : (blockIdx.z == 1) ? W1 : W2;
    float*       C = (blockIdx.z == 0) ? C0 : (blockIdx.z == 1) ? C1 : C2;

    const int tid = threadIdx.x;
    const int tx  = tid & 15;
    const int ty  = tid >> 4;
    const int r0  = ty << 3;              // 8 output rows
    const int c0  = tx << 3;              // 8 output cols
    const int bm  = blockIdx.y << 7;
    const int bn  = blockIdx.x << 7;

    const int row0 = tid >> 2;            // 0..63 (staging row; +64 2nd pass)
    const int kq   = (tid & 3) << 2;      // k quad

    u64 acc[4][8];                        // 4 row-pairs x 8 cols
#pragma unroll
    for (int i = 0; i < 4; i++)
#pragma unroll
        for (int j = 0; j < 8; j++) acc[i][j] = 0ull;

    const float* pA = A + (size_t)(bm + row0) * DMODEL + kq;
    const float* pB = B + (size_t)(bn + row0) * DMODEL + kq;

    float4 a0 = *(const float4*)pA;
    float4 a1 = *(const float4*)(pA + 64 * DMODEL);
    float4 b0 = *(const float4*)pB;
    float4 b1 = *(const float4*)(pB + 64 * DMODEL);

    for (int c = 0; c < 64; c++) {
        __syncthreads();                  // previous compute done with smem
        As[kq + 0][row0] = a0.x; As[kq + 1][row0] = a0.y;
        As[kq + 2][row0] = a0.z; As[kq + 3][row0] = a0.w;
        As[kq + 0][row0 + 64] = a1.x; As[kq + 1][row0 + 64] = a1.y;
        As[kq + 2][row0 + 64] = a1.z; As[kq + 3][row0 + 64] = a1.w;

        *(float2*)&Bs[kq + 0][2 * row0] = make_float2(b0.x, b0.x);
        *(float2*)&Bs[kq + 1][2 * row0] = make_float2(b0.y, b0.y);
        *(float2*)&Bs[kq + 2][2 * row0] = make_float2(b0.z, b0.z);
        *(float2*)&Bs[kq + 3][2 * row0] = make_float2(b0.w, b0.w);
        *(float2*)&Bs[kq + 0][2 * (row0 + 64)] = make_float2(b1.x, b1.x);
        *(float2*)&Bs[kq + 1][2 * (row0 + 64)] = make_float2(b1.y, b1.y);
        *(float2*)&Bs[kq + 2][2 * (row0 + 64)] = make_float2(b1.z, b1.z);
        *(float2*)&Bs[kq + 3][2 * (row0 + 64)] = make_float2(b1.w, b1.w);

        if (c < 63) {                     // prefetch next chunk (overlaps compute)
            pA += 16; pB += 16;
            a0 = *(const float4*)pA;
            a1 = *(const float4*)(pA + 64 * DMODEL);
            b0 = *(const float4*)pB;
            b1 = *(const float4*)(pB + 64 * DMODEL);
        }
        __syncthreads();

#pragma unroll
        for (int k = 0; k < 16; k++) {
            ulonglong2 aA = *(const ulonglong2*)&As[k][r0];
            ulonglong2 aB = *(const ulonglong2*)&As[k][r0 + 4];
            u64 ap[4] = {aA.x, aA.y, aB.x, aB.y};
            ulonglong2 d0 = *(const ulonglong2*)&Bs[k][2 * c0];
            ulonglong2 d1 = *(const ulonglong2*)&Bs[k][2 * c0 + 4];
            ulonglong2 d2 = *(const ulonglong2*)&Bs[k][2 * c0 + 8];
            ulonglong2 d3 = *(const ulonglong2*)&Bs[k][2 * c0 + 12];
            u64 bd[8] = {d0.x, d0.y, d1.x, d1.y, d2.x, d2.y, d3.x, d3.y};
#pragma unroll
            for (int i = 0; i < 4; i++)
#pragma unroll
                for (int j = 0; j < 8; j++)
                    fma2(acc[i][j], ap[i], bd[j]);
        }
    }

#pragma unroll
    for (int ip = 0; ip < 4; ip++) {
        float lo[8], hi[8];
#pragma unroll
        for (int j = 0; j < 8; j++) {
            float2 t = unpk2(acc[ip][j]);
            lo[j] = t.x; hi[j] = t.y;
        }
        float* cr0 = C + (size_t)(bm + r0 + 2 * ip) * DMODEL + bn + c0;
        float* cr1 = cr0 + DMODEL;
        *(float4*)(cr0)     = make_float4(lo[0], lo[1], lo[2], lo[3]);
        *(float4*)(cr0 + 4) = make_float4(lo[4], lo[5], lo[6], lo[7]);
        *(float4*)(cr1)     = make_float4(hi[0], hi[1], hi[2], hi[3]);
        *(float4*)(cr1 + 4) = make_float4(hi[4], hi[5], hi[6], hi[7]);
    }
}

// =========================================================================
// FFMA2 flash attention + rotation/valve epilogue.
// 64 queries x 128-key tiles, 256 threads.
//   S fragment: 4 rows x 8 cols (4 col-pairs), Q staged duplicated+scaled.
//   P stored duplicated [q][2*key] -> PV reads dup pairs via LDS.128.
//   O fragment: 4 rows x 4 cols (2 col-pairs), V pairs native.
// =========================================================================
#define SM_QD 0                       // Qd [64][132]  (dup q, scaled)
#define SM_KS 8448                    // Ks [64][132]  (d-major keys)
#define SM_VS 16896                   // Vs [128][68]
#define SM_SD 25600                   // Sd [64][264]  (dup P)
#define ATTN_SMEM ((25600 + 64 * 264) * 4)   // 169,984 B

__global__ __launch_bounds__(256)
void attn_f2(const float* __restrict__ Q, const float* __restrict__ Kg,
             const float* __restrict__ Vg,
             const float* __restrict__ beta_, const float* __restrict__ inval,
             const float* __restrict__ outval, const float* __restrict__ chiv,
             float* __restrict__ out)
{
    extern __shared__ __align__(16) float sm[];
    float* Qd = sm + SM_QD;
    float* Ks = sm + SM_KS;
    float* Vs = sm + SM_VS;
    float* Sd = sm + SM_SD;

    const int h   = blockIdx.y;
    const int b   = blockIdx.z;
    const int q0  = blockIdx.x << 6;
    const int tid = threadIdx.x;
    const int tx  = tid & 15;
    const int ty  = tid >> 4;
    const int r0  = ty << 2;          // 4 query rows
    const int c0  = tx << 3;          // 8 key cols (S)
    const int c0o = tx << 2;          // 4 dh cols (O)

    const float* qb = Q  + ((size_t)(b * T_SEQ + q0)) * DMODEL + h * DHEAD;
    const float* kb = Kg + ((size_t)(b * T_SEQ))      * DMODEL + h * DHEAD;
    const float* vb = Vg + ((size_t)(b * T_SEQ))      * DMODEL + h * DHEAD;

    // ---- stage Q duplicated + pre-scaled by 1/sqrt(dh) = 0.125 ----
#pragma unroll
    for (int i = 0; i < 4; i++) {
        int f  = tid + (i << 8);
        int q  = f >> 4;              // 0..63
        int dq = (f & 15) << 2;
        float4 v = *(const float4*)(qb + (size_t)q * DMODEL + dq);
        *(float2*)&Qd[(dq + 0) * 132 + 2 * q] = make_float2(v.x * 0.125f, v.x * 0.125f);
        *(float2*)&Qd[(dq + 1) * 132 + 2 * q] = make_float2(v.y * 0.125f, v.y * 0.125f);
        *(float2*)&Qd[(dq + 2) * 132 + 2 * q] = make_float2(v.z * 0.125f, v.z * 0.125f);
        *(float2*)&Qd[(dq + 3) * 132 + 2 * q] = make_float2(v.w * 0.125f, v.w * 0.125f);
    }

    float m_i[4] = {-1e30f, -1e30f, -1e30f, -1e30f};
    float l_i[4] = {0.f, 0.f, 0.f, 0.f};
    u64 o2[4][2];
#pragma unroll
    for (int i = 0; i < 4; i++) { o2[i][0] = 0ull; o2[i][1] = 0ull; }

    for (int kt = 0; kt < T_SEQ / 128; kt++) {
        __syncthreads();              // prior tile's reads of Ks/Vs done
        const float* kbt = kb + (size_t)kt * 128 * DMODEL;
        const float* vbt = vb + (size_t)kt * 128 * DMODEL;
#pragma unroll
        for (int i = 0; i < 8; i++) {
            int f   = tid + (i << 8);
            int key = f >> 4;         // 0..127
            int dq  = (f & 15) << 2;
            float4 kv = *(const float4*)(kbt + (size_t)key * DMODEL + dq);
            Ks[(dq + 0) * 132 + key] = kv.x;
            Ks[(dq + 1) * 132 + key] = kv.y;
            Ks[(dq + 2) * 132 + key] = kv.z;
            Ks[(dq + 3) * 132 + key] = kv.w;
            float4 vv = *(const float4*)(vbt + (size_t)key * DMODEL + dq);
            *(float4*)&Vs[key * 68 + dq] = vv;
        }
        __syncthreads();

        // ---- S = (Q/8) K^T : 4x8 fragment as 4x4 col-pairs ----
        u64 s2[4][4];
#pragma unroll
        for (int i = 0; i < 4; i++)
#pragma unroll
            for (int jp = 0; jp < 4; jp++) s2[i][jp] = 0ull;

#pragma unroll 4
        for (int d = 0; d < 64; d++) {
            ulonglong2 qa = *(const ulonglong2*)&Qd[d * 132 + 2 * r0];
            ulonglong2 qbp = *(const ulonglong2*)&Qd[d * 132 + 2 * r0 + 4];
            ulonglong2 ka = *(const ulonglong2*)&Ks[d * 132 + c0];
            ulonglong2 kbp2 = *(const ulonglong2*)&Ks[d * 132 + c0 + 4];
            u64 qd_[4] = {qa.x, qa.y, qbp.x, qbp.y};
            u64 kp_[4] = {ka.x, ka.y, kbp2.x, kbp2.y};
#pragma unroll
            for (int i = 0; i < 4; i++)
#pragma unroll
                for (int jp = 0; jp < 4; jp++)
                    fma2(s2[i][jp], qd_[i], kp_[jp]);
        }

        // ---- online softmax (row groups = 16-lane half-warps) ----
#pragma unroll
        for (int i = 0; i < 4; i++) {
            float2 e0 = unpk2(s2[i][0]);
            float2 e1 = unpk2(s2[i][1]);
            float2 e2 = unpk2(s2[i][2]);
            float2 e3 = unpk2(s2[i][3]);
            float s0 = e0.x, s1 = e0.y, s2a = e1.x, s3 = e1.y;
            float s4 = e2.x, s5 = e2.y, s6 = e3.x, s7 = e3.y;
            float mx = fmaxf(fmaxf(fmaxf(s0, s1), fmaxf(s2a, s3)),
                             fmaxf(fmaxf(s4, s5), fmaxf(s6, s7)));
#pragma unroll
            for (int off = 8; off > 0; off >>= 1)
                mx = fmaxf(mx, __shfl_xor_sync(0xffffffffu, mx, off));
            float nm = fmaxf(m_i[i], mx);
            float al = __expf(m_i[i] - nm);
            float p0 = __expf(s0 - nm), p1 = __expf(s1 - nm);
            float p2 = __expf(s2a - nm), p3 = __expf(s3 - nm);
            float p4 = __expf(s4 - nm), p5 = __expf(s5 - nm);
            float p6 = __expf(s6 - nm), p7 = __expf(s7 - nm);
            float ps = ((p0 + p1) + (p2 + p3)) + ((p4 + p5) + (p6 + p7));
#pragma unroll
            for (int off = 8; off > 0; off >>= 1)
                ps += __shfl_xor_sync(0xffffffffu, ps, off);
            l_i[i] = l_i[i] * al + ps;
            m_i[i] = nm;
            u64 a2 = dup2(al);
            o2[i][0] = mul2(o2[i][0], a2);
            o2[i][1] = mul2(o2[i][1], a2);
            // store P duplicated: Sd[q][2*key]
            float* sr = Sd + (r0 + i) * 264 + 2 * c0;
            *(float2*)(sr +  0) = make_float2(p0, p0);
            *(float2*)(sr +  2) = make_float2(p1, p1);
            *(float2*)(sr +  4) = make_float2(p2, p2);
            *(float2*)(sr +  6) = make_float2(p3, p3);
            *(float2*)(sr +  8) = make_float2(p4, p4);
            *(float2*)(sr + 10) = make_float2(p5, p5);
            *(float2*)(sr + 12) = make_float2(p6, p6);
            *(float2*)(sr + 14) = make_float2(p7, p7);
        }
        __syncwarp();     // P producer/consumer are the same half-warp

        // ---- O += P V ----
#pragma unroll 2
        for (int kk = 0; kk < 128; kk += 2) {
            u64 pd0[4], pd1[4];
#pragma unroll
            for (int i = 0; i < 4; i++) {
                ulonglong2 t = *(const ulonglong2*)&Sd[(r0 + i) * 264 + 2 * kk];
                pd0[i] = t.x; pd1[i] = t.y;
            }
            ulonglong2 v0 = *(const ulonglong2*)&Vs[kk * 68 + c0o];
            ulonglong2 v1 = *(const ulonglong2*)&Vs[(kk + 1) * 68 + c0o];
#pragma unroll
            for (int i = 0; i < 4; i++) {
                fma2(o2[i][0], pd0[i], v0.x);
                fma2(o2[i][1], pd0[i], v0.y);
                fma2(o2[i][0], pd1[i], v1.x);
                fma2(o2[i][1], pd1[i], v1.y);
            }
        }
        __syncwarp();     // PV reads of Sd done before next-tile overwrite
    }
    __syncthreads();      // all reads of Qd done -> reuse as O staging

    // ---- per-head constants ----
    float bsig = 1.f / (1.f + expf(-beta_[h]));
    float sa, ca;
    sincosf(PI_F * bsig, &sa, &ca);
    float iv  = 1.f / (1.f + expf(-inval[h]));
    float ov  = 1.f / (1.f + expf(-outval[h]));
    float gch = tanhf(chiv[h]);
    float fac = iv * ov * gch;        // rotation is linear: fold into one factor

    // stage normalized O into Qd region: Os[row][col], stride 68
#pragma unroll
    for (int i = 0; i < 4; i++) {
        float inv = 1.f / l_i[i];
        float2 u0 = unpk2(o2[i][0]);
        float2 u1 = unpk2(o2[i][1]);
        float* orow = Qd + (r0 + i) * 68 + c0o;
        orow[0] = u0.x * inv; orow[1] = u0.y * inv;
        orow[2] = u1.x * inv; orow[3] = u1.y * inv;
    }
    __syncthreads();

    // rotate halves (j, j+32), write [B,T,D] combined layout
    float* ob = out + ((size_t)(b * T_SEQ + q0)) * DMODEL + h * DHEAD;
#pragma unroll
    for (int it = 0; it < 8; it++) {
        int p = tid + (it << 8);
        int r = p >> 5;
        int j = p & 31;
        float xr = Qd[r * 68 + j];
        float xi = Qd[r * 68 + j + 32];
        ob[(size_t)r * DMODEL + j]      = (xr * ca - xi * sa) * fac;
        ob[(size_t)r * DMODEL + j + 32] = (xr * sa + xi * ca) * fac;
    }
}

// =========================================================================
extern "C" void kernel_launch(void* const* d_in, const int* in_sizes, int n_in,
                              void* d_out, int out_size)
{
    (void)in_sizes; (void)n_in; (void)out_size;

    const float* x    = (const float*)d_in[0];
    const float* Wq   = (const float*)d_in[1];
    const float* Wk   = (const float*)d_in[2];
    const float* Wv   = (const float*)d_in[3];
    const float* We   = (const float*)d_in[4];
    const float* beta = (const float*)d_in[5];
    const float* ivv  = (const float*)d_in[6];
    const float* ovv  = (const float*)d_in[7];
    const float* chi  = (const float*)d_in[8];
    float* out = (float*)d_out;

    float *qp, *kp, *vp, *ap;
    cudaGetSymbolAddress((void**)&qp, g_q);
    cudaGetSymbolAddress((void**)&kp, g_k);
    cudaGetSymbolAddress((void**)&vp, g_v);
    cudaGetSymbolAddress((void**)&ap, g_ao);

    cudaFuncSetAttribute(attn_f2, cudaFuncAttributeMaxDynamicSharedMemorySize,
                         (int)ATTN_SMEM);

    dim3 gqkv(DMODEL / 128, MROWS / 128, 3);   // (8, 32, 3) fused Q/K/V
    gemm_f2<<<gqkv, 256>>>(x, Wq, Wk, Wv, qp, kp, vp);

    dim3 ga(T_SEQ / 64, NHEADS, BATCH);        // (32, 16, 2)
    attn_f2<<<ga, 256, ATTN_SMEM>>>(qp, kp, vp, beta, ivv, ovv, chi, ap);

    dim3 go(DMODEL / 128, MROWS / 128, 1);     // (8, 32, 1) output proj
    gemm_f2<<<go, 256>>>(ap, We, We, We, out, out, out);
}

// round 12
// speedup vs baseline: 2.6479x; 2.6448x over previous
#include <cuda_runtime.h>
#include <cuda_bf16.h>
#include <math.h>
#include <stdint.h>

#define T_SEQ   2048
#define BATCH   2
#define DMODEL  1024
#define NHEADS  16
#define DHEAD   64
#define MROWS   (BATCH * T_SEQ)   // 4096
#define PI_F    3.14159265358979323846f

// ---------------- device scratch (no allocations allowed) ----------------
__device__ float g_q [MROWS * DMODEL];
__device__ float g_k [MROWS * DMODEL];
__device__ float g_v [MROWS * DMODEL];
__device__ float g_ao[MROWS * DMODEL];

// =========================================================================
// helpers
// =========================================================================
__device__ __forceinline__ uint32_t smem_u32(const void* p) {
    uint32_t a;
    asm("{ .reg .u64 t; cvta.to.shared.u64 t, %1; cvt.u32.u64 %0, t; }"
        : "=r"(a) : "l"(p));
    return a;
}

// swizzled byte offset of the 16B quad holding (row, half-of-16-k) in a
// [rows][16] bf16 chunk. Guarantees the 8 rows of any ldmatrix 8x8 matrix
// (fixed half) hit 8 distinct 16B bank groups.
__device__ __forceinline__ uint32_t qoff(int row, int half) {
    return (uint32_t)((((row >> 3) << 4) + ((row & 7) << 1) +
                       (half ^ ((row >> 2) & 1))) << 4);
}

#define LDM4(r, addr) \
    asm volatile("ldmatrix.sync.aligned.m8n8.x4.shared.b16 {%0,%1,%2,%3}, [%4];" \
        : "=r"((r)[0]), "=r"((r)[1]), "=r"((r)[2]), "=r"((r)[3]) : "r"(addr))

#define MMA_BF16(d, a, b0_, b1_) \
    asm volatile("mma.sync.aligned.m16n8k16.row.col.f32.bf16.bf16.f32 " \
        "{%0,%1,%2,%3},{%4,%5,%6,%7},{%8,%9},{%0,%1,%2,%3};" \
        : "+f"((d)[0]), "+f"((d)[1]), "+f"((d)[2]), "+f"((d)[3]) \
        : "r"((a)[0]), "r"((a)[1]), "r"((a)[2]), "r"((a)[3]), \
          "r"(b0_), "r"(b1_))

// fp32x4 -> bf16 hi (rn) + bf16 lo (rn of residual), packed as uint2 (8B)
__device__ __forceinline__ void cvt_hilo(float4 v, uint2& hi, uint2& lo) {
    __nv_bfloat162 h01 = __floats2bfloat162_rn(v.x, v.y);
    __nv_bfloat162 h23 = __floats2bfloat162_rn(v.z, v.w);
    float2 f01 = __bfloat1622float2(h01);
    float2 f23 = __bfloat1622float2(h23);
    __nv_bfloat162 l01 = __floats2bfloat162_rn(v.x - f01.x, v.y - f01.y);
    __nv_bfloat162 l23 = __floats2bfloat162_rn(v.z - f23.x, v.w - f23.y);
    hi.x = *reinterpret_cast<unsigned*>(&h01);
    hi.y = *reinterpret_cast<unsigned*>(&h23);
    lo.x = *reinterpret_cast<unsigned*>(&l01);
    lo.y = *reinterpret_cast<unsigned*>(&l23);
}

// =========================================================================
// bf16x3 mma.sync GEMM (NT): C[m,n] = sum_k A[m,k] * B[n,k]
// 128x128 CTA tile, 256 thr, warp tile 32x64, BK=16.
// D = Ah*Bh + Al*Bh + Ah*Bl (fp32 accum) -> ~fp32-quality result.
// grid.z selects among up to 3 (B, C) pairs (fused Q/K/V projections).
// =========================================================================
__global__ __launch_bounds__(256)
void gemm_bf16x3(const float* __restrict__ A,
                 const float* __restrict__ W0, const float* __restrict__ W1,
                 const float* __restrict__ W2,
                 float* __restrict__ C0, float* __restrict__ C1,
                 float* __restrict__ C2)
{
    __shared__ __align__(16) __nv_bfloat16 sAh[2048];   // [128 m][16 k] swizzled
    __shared__ __align__(16) __nv_bfloat16 sAl[2048];
    __shared__ __align__(16) __nv_bfloat16 sBh[2048];   // [128 n][16 k] swizzled
    __shared__ __align__(16) __nv_bfloat16 sBl[2048];

    const float* B = (blockIdx.z == 0) ? W0 : (blockIdx.z == 1) ? W1 : W2;
    float*       C = (blockIdx.z == 0) ? C0 : (blockIdx.z == 1) ? C1 : C2;

    const int tid  = threadIdx.x;
    const int warp = tid >> 5;
    const int lane = tid & 31;
    const int wm   = (warp & 3) << 5;     // 0,32,64,96
    const int wn   = (warp >> 2) << 6;    // 0,64
    const int bm   = blockIdx.y << 7;
    const int bn   = blockIdx.x << 7;

    // ---- loader mapping: thread -> (row, float4-within-row) ----
    const int row0 = tid >> 2;            // 0..63 (and +64 on second slot)
    const int f4   = tid & 3;
    const uint32_t st0 = qoff(row0,      f4 >> 1) + (uint32_t)((f4 & 1) << 3);
    const uint32_t st1 = qoff(row0 + 64, f4 >> 1) + (uint32_t)((f4 & 1) << 3);

    char* cAh = (char*)sAh; char* cAl = (char*)sAl;
    char* cBh = (char*)sBh; char* cBl = (char*)sBl;

    // ---- ldmatrix smem addresses (chunk-invariant) ----
    const uint32_t bAh = smem_u32(sAh), bAl = smem_u32(sAl);
    const uint32_t bBh = smem_u32(sBh), bBl = smem_u32(sBl);
    uint32_t aOff[2], bOff[4];
    {
        // A x4: matrices (m0-7,h0)(m8-15,h0)(m0-7,h1)(m8-15,h1)
        int r  = (lane & 7) + ((lane >> 3) & 1) * 8;
        int hA = (lane >> 4) & 1;
        aOff[0] = qoff(wm + r,      hA);
        aOff[1] = qoff(wm + 16 + r, hA);
        // B x4: matrices (n0-7,h0)(n0-7,h1)(n8-15,h0)(n8-15,h1)
        int rn_ = (lane & 7) + ((lane >> 4) & 1) * 8;
        int hB  = (lane >> 3) & 1;
#pragma unroll
        for (int j = 0; j < 4; j++)
            bOff[j] = qoff(wn + 16 * j + rn_, hB);
    }

    float acc[2][8][4];
#pragma unroll
    for (int i = 0; i < 2; i++)
#pragma unroll
        for (int j = 0; j < 8; j++)
#pragma unroll
            for (int e = 0; e < 4; e++) acc[i][j][e] = 0.f;

    const float* pA = A + (size_t)(bm + row0) * DMODEL + f4 * 4;
    const float* pB = B + (size_t)(bn + row0) * DMODEL + f4 * 4;

    float4 ra0 = *(const float4*)pA;
    float4 ra1 = *(const float4*)(pA + 64 * DMODEL);
    float4 rb0 = *(const float4*)pB;
    float4 rb1 = *(const float4*)(pB + 64 * DMODEL);

    for (int c = 0; c < DMODEL / 16; c++) {
        __syncthreads();                       // prior chunk's ldmatrix done
        uint2 hi, lo;
        cvt_hilo(ra0, hi, lo);
        *(uint2*)(cAh + st0) = hi; *(uint2*)(cAl + st0) = lo;
        cvt_hilo(ra1, hi, lo);
        *(uint2*)(cAh + st1) = hi; *(uint2*)(cAl + st1) = lo;
        cvt_hilo(rb0, hi, lo);
        *(uint2*)(cBh + st0) = hi; *(uint2*)(cBl + st0) = lo;
        cvt_hilo(rb1, hi, lo);
        *(uint2*)(cBh + st1) = hi; *(uint2*)(cBl + st1) = lo;

        if (c < DMODEL / 16 - 1) {             // prefetch next chunk
            pA += 16; pB += 16;
            ra0 = *(const float4*)pA;
            ra1 = *(const float4*)(pA + 64 * DMODEL);
            rb0 = *(const float4*)pB;
            rb1 = *(const float4*)(pB + 64 * DMODEL);
        }
        __syncthreads();

        uint32_t Ah[2][4], Al[2][4], Bh[4][4], Bl[4][4];
        LDM4(Ah[0], bAh + aOff[0]);  LDM4(Ah[1], bAh + aOff[1]);
        LDM4(Al[0], bAl + aOff[0]);  LDM4(Al[1], bAl + aOff[1]);
#pragma unroll
        for (int g = 0; g < 4; g++) { LDM4(Bh[g], bBh + bOff[g]); }
#pragma unroll
        for (int g = 0; g < 4; g++) { LDM4(Bl[g], bBl + bOff[g]); }

        // term 1: Ah * Bh
#pragma unroll
        for (int i = 0; i < 2; i++)
#pragma unroll
            for (int j = 0; j < 8; j++) {
                const uint32_t* bg = Bh[j >> 1] + ((j & 1) << 1);
                MMA_BF16(acc[i][j], Ah[i], bg[0], bg[1]);
            }
        // term 2: Al * Bh
#pragma unroll
        for (int i = 0; i < 2; i++)
#pragma unroll
            for (int j = 0; j < 8; j++) {
                const uint32_t* bg = Bh[j >> 1] + ((j & 1) << 1);
                MMA_BF16(acc[i][j], Al[i], bg[0], bg[1]);
            }
        // term 3: Ah * Bl
#pragma unroll
        for (int i = 0; i < 2; i++)
#pragma unroll
            for (int j = 0; j < 8; j++) {
                const uint32_t* bg = Bl[j >> 1] + ((j & 1) << 1);
                MMA_BF16(acc[i][j], Ah[i], bg[0], bg[1]);
            }
    }

    // ---- writeback: fragment (m16n8) -> rows (l>>2, +8), cols 2(l&3)+{0,1}
    const int fr = lane >> 2;
    const int fc = (lane & 3) << 1;
#pragma unroll
    for (int i = 0; i < 2; i++) {
#pragma unroll
        for (int j = 0; j < 8; j++) {
            float* c0p = C + (size_t)(bm + wm + i * 16 + fr) * DMODEL
                           + bn + wn + j * 8 + fc;
            *(float2*)c0p                 = make_float2(acc[i][j][0], acc[i][j][1]);
            *(float2*)(c0p + 8 * DMODEL)  = make_float2(acc[i][j][2], acc[i][j][3]);
        }
    }
}

// =========================================================================
// Flash attention + rotation/valve epilogue (R6 version, proven correct).
// =========================================================================
#define PS 68   // smem row stride (floats)

__global__ __launch_bounds__(256)
void attn_kernel(const float* __restrict__ Q, const float* __restrict__ Kg,
                 const float* __restrict__ Vg,
                 const float* __restrict__ beta_, const float* __restrict__ inval,
                 const float* __restrict__ outval, const float* __restrict__ chiv,
                 float* __restrict__ out)
{
    extern __shared__ float sm[];
    float* Qs = sm;                 // [d][row]   64 x PS
    float* Ks = sm + 64 * PS;       // [d][key]   64 x PS
    float* Vs = sm + 2 * 64 * PS;   // [key][d]   64 x PS
    float* Ss = sm + 3 * 64 * PS;   // [key][row] 64 x PS (reused as Os)

    const int h   = blockIdx.y;
    const int b   = blockIdx.z;
    const int q0  = blockIdx.x << 6;
    const int tid = threadIdx.x;
    const int tx  = tid & 15;
    const int tyf = tid >> 4;
    const int r0  = tyf << 2;
    const int c0  = tx << 2;

    const float* qb = Q  + ((size_t)(b * T_SEQ + q0)) * DMODEL + h * DHEAD;
    const float* kb = Kg + ((size_t)(b * T_SEQ))      * DMODEL + h * DHEAD;
    const float* vb = Vg + ((size_t)(b * T_SEQ))      * DMODEL + h * DHEAD;

    const int lrow = tid >> 4;
    const int ldq  = (tid & 15) << 2;

#pragma unroll
    for (int i = 0; i < 4; i++) {
        int row = lrow + (i << 4);
        float4 v = *(const float4*)(qb + (size_t)row * DMODEL + ldq);
        Qs[(ldq + 0) * PS + row] = v.x;
        Qs[(ldq + 1) * PS + row] = v.y;
        Qs[(ldq + 2) * PS + row] = v.z;
        Qs[(ldq + 3) * PS + row] = v.w;
    }

    float m_i[4] = {-1e30f, -1e30f, -1e30f, -1e30f};
    float l_i[4] = {0.f, 0.f, 0.f, 0.f};
    float o[4][4];
#pragma unroll
    for (int i = 0; i < 4; i++)
#pragma unroll
        for (int j = 0; j < 4; j++) o[i][j] = 0.f;

    for (int kt = 0; kt < T_SEQ / 64; kt++) {
        __syncthreads();
        const float* kbt = kb + (size_t)kt * 64 * DMODEL;
        const float* vbt = vb + (size_t)kt * 64 * DMODEL;
#pragma unroll
        for (int i = 0; i < 4; i++) {
            int row = lrow + (i << 4);
            float4 v = *(const float4*)(kbt + (size_t)row * DMODEL + ldq);
            Ks[(ldq + 0) * PS + row] = v.x;
            Ks[(ldq + 1) * PS + row] = v.y;
            Ks[(ldq + 2) * PS + row] = v.z;
            Ks[(ldq + 3) * PS + row] = v.w;
            float4 w = *(const float4*)(vbt + (size_t)row * DMODEL + ldq);
            *(float4*)(Vs + row * PS + ldq) = w;
        }
        __syncthreads();

        float s[4][4];
#pragma unroll
        for (int i = 0; i < 4; i++)
#pragma unroll
            for (int j = 0; j < 4; j++) s[i][j] = 0.f;

#pragma unroll 8
        for (int d = 0; d < 64; d++) {
            float4 a  = *(const float4*)(Qs + d * PS + r0);
            float4 bb = *(const float4*)(Ks + d * PS + c0);
            float ar[4] = {a.x, a.y, a.z, a.w};
            float br[4] = {bb.x, bb.y, bb.z, bb.w};
#pragma unroll
            for (int i = 0; i < 4; i++)
#pragma unroll
                for (int j = 0; j < 4; j++)
                    s[i][j] += ar[i] * br[j];
        }

#pragma unroll
        for (int i = 0; i < 4; i++) {
#pragma unroll
            for (int j = 0; j < 4; j++) s[i][j] *= 0.125f;
            float mx = fmaxf(fmaxf(s[i][0], s[i][1]), fmaxf(s[i][2], s[i][3]));
#pragma unroll
            for (int off = 8; off > 0; off >>= 1)
                mx = fmaxf(mx, __shfl_xor_sync(0xffffffffu, mx, off));
            float nm = fmaxf(m_i[i], mx);
            float al = __expf(m_i[i] - nm);
            float ps = 0.f;
#pragma unroll
            for (int j = 0; j < 4; j++) {
                float p = __expf(s[i][j] - nm);
                s[i][j] = p;
                ps += p;
            }
#pragma unroll
            for (int off = 8; off > 0; off >>= 1)
                ps += __shfl_xor_sync(0xffffffffu, ps, off);
            l_i[i] = l_i[i] * al + ps;
            m_i[i] = nm;
#pragma unroll
            for (int j = 0; j < 4; j++) o[i][j] *= al;
#pragma unroll
            for (int j = 0; j < 4; j++)
                Ss[(c0 + j) * PS + r0 + i] = s[i][j];
        }
        __syncthreads();

#pragma unroll 8
        for (int kk = 0; kk < 64; kk++) {
            float4 a  = *(const float4*)(Ss + kk * PS + r0);
            float4 vv = *(const float4*)(Vs + kk * PS + c0);
            float ar[4] = {a.x, a.y, a.z, a.w};
            float br[4] = {vv.x, vv.y, vv.z, vv.w};
#pragma unroll
            for (int i = 0; i < 4; i++)
#pragma unroll
                for (int j = 0; j < 4; j++)
                    o[i][j] += ar[i] * br[j];
        }
    }
    __syncthreads();

    float bsig = 1.f / (1.f + expf(-beta_[h]));
    float sa, ca;
    sincosf(PI_F * bsig, &sa, &ca);
    float iv  = 1.f / (1.f + expf(-inval[h]));
    float ov  = 1.f / (1.f + expf(-outval[h]));
    float gch = tanhf(chiv[h]);
    float fac = iv * ov * gch;

#pragma unroll
    for (int i = 0; i < 4; i++) {
        float inv = 1.f / l_i[i];
#pragma unroll
        for (int j = 0; j < 4; j++)
            Ss[(r0 + i) * PS + c0 + j] = o[i][j] * inv;
    }
    __syncthreads();

    float* ob = out + ((size_t)(b * T_SEQ + q0)) * DMODEL + h * DHEAD;
#pragma unroll
    for (int it = 0; it < 8; it++) {
        int p = tid + (it << 8);
        int r = p >> 5;
        int j = p & 31;
        float xr = Ss[r * PS + j];
        float xi = Ss[r * PS + j + 32];
        ob[(size_t)r * DMODEL + j]      = (xr * ca - xi * sa) * fac;
        ob[(size_t)r * DMODEL + j + 32] = (xr * sa + xi * ca) * fac;
    }
}

#define ATTN_SMEM (4 * 64 * PS * sizeof(float))   // 69,632 B

// =========================================================================
extern "C" void kernel_launch(void* const* d_in, const int* in_sizes, int n_in,
                              void* d_out, int out_size)
{
    (void)in_sizes; (void)n_in; (void)out_size;

    const float* x    = (const float*)d_in[0];
    const float* Wq   = (const float*)d_in[1];
    const float* Wk   = (const float*)d_in[2];
    const float* Wv   = (const float*)d_in[3];
    const float* We   = (const float*)d_in[4];
    const float* beta = (const float*)d_in[5];
    const float* ivv  = (const float*)d_in[6];
    const float* ovv  = (const float*)d_in[7];
    const float* chi  = (const float*)d_in[8];
    float* out = (float*)d_out;

    float *qp, *kp, *vp, *ap;
    cudaGetSymbolAddress((void**)&qp, g_q);
    cudaGetSymbolAddress((void**)&kp, g_k);
    cudaGetSymbolAddress((void**)&vp, g_v);
    cudaGetSymbolAddress((void**)&ap, g_ao);

    cudaFuncSetAttribute(attn_kernel, cudaFuncAttributeMaxDynamicSharedMemorySize,
                         (int)ATTN_SMEM);

    dim3 gqkv(DMODEL / 128, MROWS / 128, 3);   // (8, 32, 3) fused Q/K/V
    gemm_bf16x3<<<gqkv, 256>>>(x, Wq, Wk, Wv, qp, kp, vp);

    dim3 ga(T_SEQ / 64, NHEADS, BATCH);        // (32, 16, 2)
    attn_kernel<<<ga, 256, ATTN_SMEM>>>(qp, kp, vp, beta, ivv, ovv, chi, ap);

    dim3 go(DMODEL / 128, MROWS / 128, 1);     // (8, 32, 1) output proj
    gemm_bf16x3<<<go, 256>>>(ap, We, We, We, out, out, out);
}

// round 13
// speedup vs baseline: 4.1758x; 1.5770x over previous
#include <cuda_runtime.h>
#include <cuda_bf16.h>
#include <math.h>
#include <stdint.h>

#define T_SEQ   2048
#define BATCH   2
#define DMODEL  1024
#define NHEADS  16
#define DHEAD   64
#define MROWS   (BATCH * T_SEQ)   // 4096
#define PI_F    3.14159265358979323846f

// ---------------- device scratch (no allocations allowed) ----------------
__device__ float g_q [MROWS * DMODEL];
__device__ float g_k [MROWS * DMODEL];
__device__ float g_v [MROWS * DMODEL];
__device__ float g_ao[MROWS * DMODEL];

// =========================================================================
// helpers
// =========================================================================
__device__ __forceinline__ uint32_t smem_u32(const void* p) {
    uint32_t a;
    asm("{ .reg .u64 t; cvta.to.shared.u64 t, %1; cvt.u32.u64 %0, t; }"
        : "=r"(a) : "l"(p));
    return a;
}

// swizzled byte offset of the 16B quad holding (row, half-of-16-k) in a
// [rows][16] bf16 chunk. The 8 rows of any ldmatrix 8x8 matrix (fixed half)
// hit 8 distinct 16B bank groups.
__device__ __forceinline__ uint32_t qoff(int row, int half) {
    return (uint32_t)((((row >> 3) << 4) + ((row & 7) << 1) +
                       (half ^ ((row >> 2) & 1))) << 4);
}

#define LDM4(r, addr) \
    asm volatile("ldmatrix.sync.aligned.m8n8.x4.shared.b16 {%0,%1,%2,%3}, [%4];" \
        : "=r"((r)[0]), "=r"((r)[1]), "=r"((r)[2]), "=r"((r)[3]) : "r"(addr))

#define MMA_BF16(d, a, b0_, b1_) \
    asm volatile("mma.sync.aligned.m16n8k16.row.col.f32.bf16.bf16.f32 " \
        "{%0,%1,%2,%3},{%4,%5,%6,%7},{%8,%9},{%0,%1,%2,%3};" \
        : "+f"((d)[0]), "+f"((d)[1]), "+f"((d)[2]), "+f"((d)[3]) \
        : "r"((a)[0]), "r"((a)[1]), "r"((a)[2]), "r"((a)[3]), \
          "r"(b0_), "r"(b1_))

// fp32x4 -> bf16 hi (rn) + bf16 lo (rn of residual), packed as uint2 (8B)
__device__ __forceinline__ void cvt_hilo(float4 v, uint2& hi, uint2& lo) {
    __nv_bfloat162 h01 = __floats2bfloat162_rn(v.x, v.y);
    __nv_bfloat162 h23 = __floats2bfloat162_rn(v.z, v.w);
    float2 f01 = __bfloat1622float2(h01);
    float2 f23 = __bfloat1622float2(h23);
    __nv_bfloat162 l01 = __floats2bfloat162_rn(v.x - f01.x, v.y - f01.y);
    __nv_bfloat162 l23 = __floats2bfloat162_rn(v.z - f23.x, v.w - f23.y);
    hi.x = *reinterpret_cast<unsigned*>(&h01);
    hi.y = *reinterpret_cast<unsigned*>(&h23);
    lo.x = *reinterpret_cast<unsigned*>(&l01);
    lo.y = *reinterpret_cast<unsigned*>(&l23);
}

// two fp32 -> packed bf16x2 hi + bf16x2 lo(residual)
__device__ __forceinline__ uint32_t pk_hilo(float a, float b, uint32_t& lo) {
    __nv_bfloat162 h = __floats2bfloat162_rn(a, b);
    float2 f = __bfloat1622float2(h);
    __nv_bfloat162 l = __floats2bfloat162_rn(a - f.x, b - f.y);
    lo = *reinterpret_cast<uint32_t*>(&l);
    return *reinterpret_cast<uint32_t*>(&h);
}

// =========================================================================
// bf16x3 mma.sync GEMM (NT) — unchanged from R12 (295 us for QKV fused).
// =========================================================================
__global__ __launch_bounds__(256)
void gemm_bf16x3(const float* __restrict__ A,
                 const float* __restrict__ W0, const float* __restrict__ W1,
                 const float* __restrict__ W2,
                 float* __restrict__ C0, float* __restrict__ C1,
                 float* __restrict__ C2)
{
    __shared__ __align__(16) __nv_bfloat16 sAh[2048];
    __shared__ __align__(16) __nv_bfloat16 sAl[2048];
    __shared__ __align__(16) __nv_bfloat16 sBh[2048];
    __shared__ __align__(16) __nv_bfloat16 sBl[2048];

    const float* B = (blockIdx.z == 0) ? W0 : (blockIdx.z == 1) ? W1 : W2;
    float*       C = (blockIdx.z == 0) ? C0 : (blockIdx.z == 1) ? C1 : C2;

    const int tid  = threadIdx.x;
    const int warp = tid >> 5;
    const int lane = tid & 31;
    const int wm   = (warp & 3) << 5;
    const int wn   = (warp >> 2) << 6;
    const int bm   = blockIdx.y << 7;
    const int bn   = blockIdx.x << 7;

    const int row0 = tid >> 2;
    const int f4   = tid & 3;
    const uint32_t st0 = qoff(row0,      f4 >> 1) + (uint32_t)((f4 & 1) << 3);
    const uint32_t st1 = qoff(row0 + 64, f4 >> 1) + (uint32_t)((f4 & 1) << 3);

    char* cAh = (char*)sAh; char* cAl = (char*)sAl;
    char* cBh = (char*)sBh; char* cBl = (char*)sBl;

    const uint32_t bAh = smem_u32(sAh), bAl = smem_u32(sAl);
    const uint32_t bBh = smem_u32(sBh), bBl = smem_u32(sBl);
    uint32_t aOff[2], bOff[4];
    {
        int r  = (lane & 7) + ((lane >> 3) & 1) * 8;
        int hA = (lane >> 4) & 1;
        aOff[0] = qoff(wm + r,      hA);
        aOff[1] = qoff(wm + 16 + r, hA);
        int rn_ = (lane & 7) + ((lane >> 4) & 1) * 8;
        int hB  = (lane >> 3) & 1;
#pragma unroll
        for (int j = 0; j < 4; j++)
            bOff[j] = qoff(wn + 16 * j + rn_, hB);
    }

    float acc[2][8][4];
#pragma unroll
    for (int i = 0; i < 2; i++)
#pragma unroll
        for (int j = 0; j < 8; j++)
#pragma unroll
            for (int e = 0; e < 4; e++) acc[i][j][e] = 0.f;

    const float* pA = A + (size_t)(bm + row0) * DMODEL + f4 * 4;
    const float* pB = B + (size_t)(bn + row0) * DMODEL + f4 * 4;

    float4 ra0 = *(const float4*)pA;
    float4 ra1 = *(const float4*)(pA + 64 * DMODEL);
    float4 rb0 = *(const float4*)pB;
    float4 rb1 = *(const float4*)(pB + 64 * DMODEL);

    for (int c = 0; c < DMODEL / 16; c++) {
        __syncthreads();
        uint2 hi, lo;
        cvt_hilo(ra0, hi, lo);
        *(uint2*)(cAh + st0) = hi; *(uint2*)(cAl + st0) = lo;
        cvt_hilo(ra1, hi, lo);
        *(uint2*)(cAh + st1) = hi; *(uint2*)(cAl + st1) = lo;
        cvt_hilo(rb0, hi, lo);
        *(uint2*)(cBh + st0) = hi; *(uint2*)(cBl + st0) = lo;
        cvt_hilo(rb1, hi, lo);
        *(uint2*)(cBh + st1) = hi; *(uint2*)(cBl + st1) = lo;

        if (c < DMODEL / 16 - 1) {
            pA += 16; pB += 16;
            ra0 = *(const float4*)pA;
            ra1 = *(const float4*)(pA + 64 * DMODEL);
            rb0 = *(const float4*)pB;
            rb1 = *(const float4*)(pB + 64 * DMODEL);
        }
        __syncthreads();

        uint32_t Ah[2][4], Al[2][4], Bh[4][4], Bl[4][4];
        LDM4(Ah[0], bAh + aOff[0]);  LDM4(Ah[1], bAh + aOff[1]);
        LDM4(Al[0], bAl + aOff[0]);  LDM4(Al[1], bAl + aOff[1]);
#pragma unroll
        for (int g = 0; g < 4; g++) { LDM4(Bh[g], bBh + bOff[g]); }
#pragma unroll
        for (int g = 0; g < 4; g++) { LDM4(Bl[g], bBl + bOff[g]); }

#pragma unroll
        for (int i = 0; i < 2; i++)
#pragma unroll
            for (int j = 0; j < 8; j++) {
                const uint32_t* bg = Bh[j >> 1] + ((j & 1) << 1);
                MMA_BF16(acc[i][j], Ah[i], bg[0], bg[1]);
            }
#pragma unroll
        for (int i = 0; i < 2; i++)
#pragma unroll
            for (int j = 0; j < 8; j++) {
                const uint32_t* bg = Bh[j >> 1] + ((j & 1) << 1);
                MMA_BF16(acc[i][j], Al[i], bg[0], bg[1]);
            }
#pragma unroll
        for (int i = 0; i < 2; i++)
#pragma unroll
            for (int j = 0; j < 8; j++) {
                const uint32_t* bg = Bl[j >> 1] + ((j & 1) << 1);
                MMA_BF16(acc[i][j], Ah[i], bg[0], bg[1]);
            }
    }

    const int fr = lane >> 2;
    const int fc = (lane & 3) << 1;
#pragma unroll
    for (int i = 0; i < 2; i++) {
#pragma unroll
        for (int j = 0; j < 8; j++) {
            float* c0p = C + (size_t)(bm + wm + i * 16 + fr) * DMODEL
                           + bn + wn + j * 8 + fc;
            *(float2*)c0p                 = make_float2(acc[i][j][0], acc[i][j][1]);
            *(float2*)(c0p + 8 * DMODEL)  = make_float2(acc[i][j][2], acc[i][j][3]);
        }
    }
}

// =========================================================================
// bf16x3 mma.sync flash attention + rotation/valve epilogue.
// CTA: 128 queries of one (b,h); 256 thr; warp = 16 q-rows x full 64-key tile.
// Q frags register-resident; P re-packed C-frag -> A-frag in registers;
// rotation done on register O-fragments (col pairs = frag pairs j, j+4).
// 3-term compensation on both QK^T and PV.
// =========================================================================
#define AT_QH 0
#define AT_QL 16384
#define AT_KH 32768
#define AT_KL 40960
#define AT_VH 49152
#define AT_VL 57344
#define ATTN_SMEM 65536

__global__ __launch_bounds__(256)
void attn_mma(const float* __restrict__ Q, const float* __restrict__ Kg,
              const float* __restrict__ Vg,
              const float* __restrict__ beta_, const float* __restrict__ inval,
              const float* __restrict__ outval, const float* __restrict__ chiv,
              float* __restrict__ out)
{
    extern __shared__ __align__(16) char smb[];

    const int h    = blockIdx.y;
    const int b    = blockIdx.z;
    const int q0   = blockIdx.x << 7;
    const int tid  = threadIdx.x;
    const int warp = tid >> 5;
    const int lane = tid & 31;
    const int wm   = warp << 4;        // warp query rows [wm, wm+16)

    const float* qb = Q  + ((size_t)(b * T_SEQ + q0)) * DMODEL + h * DHEAD;
    const float* kb = Kg + ((size_t)(b * T_SEQ))      * DMODEL + h * DHEAD;
    const float* vb = Vg + ((size_t)(b * T_SEQ))      * DMODEL + h * DHEAD;

    // ---- stage Q (pre-scaled 0.125) hi/lo: 4 chunks of [128][16] ----
#pragma unroll
    for (int i = 0; i < 8; i++) {
        int f   = tid + (i << 8);
        int row = f >> 4;              // 0..127
        int q4  = f & 15;              // float4 within row
        float4 v = *(const float4*)(qb + (size_t)row * DMODEL + (q4 << 2));
        v.x *= 0.125f; v.y *= 0.125f; v.z *= 0.125f; v.w *= 0.125f;
        uint2 hi, lo;
        cvt_hilo(v, hi, lo);
        uint32_t off = ((uint32_t)(q4 >> 2) << 12) + qoff(row, (q4 >> 1) & 1)
                     + ((uint32_t)(q4 & 1) << 3);
        *(uint2*)(smb + AT_QH + off) = hi;
        *(uint2*)(smb + AT_QL + off) = lo;
    }
    __syncthreads();

    // ---- fragment smem addresses ----
    const uint32_t sbase = smem_u32(smb);
    uint32_t aOffQ[4], bOff[4];
    {
        int r  = (lane & 7) + ((lane >> 3) & 1) * 8;
        int hA = (lane >> 4) & 1;
#pragma unroll
        for (int c = 0; c < 4; c++)
            aOffQ[c] = ((uint32_t)c << 12) + qoff(wm + r, hA);
        int rn_ = (lane & 7) + ((lane >> 4) & 1) * 8;
        int hB  = (lane >> 3) & 1;
#pragma unroll
        for (int g = 0; g < 4; g++)
            bOff[g] = qoff(16 * g + rn_, hB);
    }

    // ---- resident Q fragments ----
    uint32_t Qh[4][4], Ql[4][4];
#pragma unroll
    for (int c = 0; c < 4; c++) {
        LDM4(Qh[c], sbase + AT_QH + aOffQ[c]);
        LDM4(Ql[c], sbase + AT_QL + aOffQ[c]);
    }

    float o[8][4];
#pragma unroll
    for (int j = 0; j < 8; j++)
#pragma unroll
        for (int e = 0; e < 4; e++) o[j][e] = 0.f;
    float m0 = -1e30f, m1 = -1e30f, l0 = 0.f, l1 = 0.f;

    for (int kt = 0; kt < T_SEQ / 64; kt++) {
        __syncthreads();   // prior tile's K/V fragment loads complete
        const float* kbt = kb + (size_t)kt * 64 * DMODEL;
        const float* vbt = vb + (size_t)kt * 64 * DMODEL;

        // K: [64 key][64 dh] hi/lo, 4 dh-chunks of [64][16]
#pragma unroll
        for (int i = 0; i < 4; i++) {
            int f   = tid + (i << 8);
            int row = f >> 4;          // key 0..63
            int q4  = f & 15;
            float4 v = *(const float4*)(kbt + (size_t)row * DMODEL + (q4 << 2));
            uint2 hi, lo;
            cvt_hilo(v, hi, lo);
            uint32_t off = ((uint32_t)(q4 >> 2) << 11) + qoff(row, (q4 >> 1) & 1)
                         + ((uint32_t)(q4 & 1) << 3);
            *(uint2*)(smb + AT_KH + off) = hi;
            *(uint2*)(smb + AT_KL + off) = lo;
        }
        // V transposed: [64 dh][64 key] hi/lo, 4 key-chunks of [64][16]
#pragma unroll
        for (int i = 0; i < 4; i++) {
            int f   = tid + (i << 8);
            int key = f >> 4;          // 0..63
            int dh0 = (f & 15) << 2;
            float4 v = *(const float4*)(vbt + (size_t)key * DMODEL + dh0);
            uint32_t cb  = ((uint32_t)(key >> 4) << 11);
            int      chf = (key >> 3) & 1;
            uint32_t el  = (uint32_t)((key & 7) << 1);
            float vv[4] = {v.x, v.y, v.z, v.w};
#pragma unroll
            for (int e = 0; e < 4; e++) {
                __nv_bfloat16 hv = __float2bfloat16(vv[e]);
                __nv_bfloat16 lv = __float2bfloat16(vv[e] - __bfloat162float(hv));
                uint32_t ad = cb + qoff(dh0 + e, chf) + el;
                *(__nv_bfloat16*)(smb + AT_VH + ad) = hv;
                *(__nv_bfloat16*)(smb + AT_VL + ad) = lv;
            }
        }
        __syncthreads();

        // ---- S = (Q/8) K^T : 8 n8 frags over 64 keys ----
        float s[8][4];
#pragma unroll
        for (int j = 0; j < 8; j++)
#pragma unroll
            for (int e = 0; e < 4; e++) s[j][e] = 0.f;

#pragma unroll
        for (int c = 0; c < 4; c++) {
            uint32_t Kh_[4][4], Kl_[4][4];
#pragma unroll
            for (int g = 0; g < 4; g++) {
                LDM4(Kh_[g], sbase + AT_KH + ((uint32_t)c << 11) + bOff[g]);
            }
#pragma unroll
            for (int g = 0; g < 4; g++) {
                LDM4(Kl_[g], sbase + AT_KL + ((uint32_t)c << 11) + bOff[g]);
            }
#pragma unroll
            for (int j = 0; j < 8; j++) {
                const uint32_t* bg = Kh_[j >> 1] + ((j & 1) << 1);
                MMA_BF16(s[j], Qh[c], bg[0], bg[1]);
            }
#pragma unroll
            for (int j = 0; j < 8; j++) {
                const uint32_t* bg = Kh_[j >> 1] + ((j & 1) << 1);
                MMA_BF16(s[j], Ql[c], bg[0], bg[1]);
            }
#pragma unroll
            for (int j = 0; j < 8; j++) {
                const uint32_t* bg = Kl_[j >> 1] + ((j & 1) << 1);
                MMA_BF16(s[j], Qh[c], bg[0], bg[1]);
            }
        }

        // ---- online softmax (rows r=lane>>2 and r+8; quad = same row) ----
        float mx0 = -1e30f, mx1 = -1e30f;
#pragma unroll
        for (int j = 0; j < 8; j++) {
            mx0 = fmaxf(mx0, fmaxf(s[j][0], s[j][1]));
            mx1 = fmaxf(mx1, fmaxf(s[j][2], s[j][3]));
        }
        mx0 = fmaxf(mx0, __shfl_xor_sync(0xffffffffu, mx0, 1));
        mx0 = fmaxf(mx0, __shfl_xor_sync(0xffffffffu, mx0, 2));
        mx1 = fmaxf(mx1, __shfl_xor_sync(0xffffffffu, mx1, 1));
        mx1 = fmaxf(mx1, __shfl_xor_sync(0xffffffffu, mx1, 2));
        float nm0 = fmaxf(m0, mx0), nm1 = fmaxf(m1, mx1);
        float al0 = __expf(m0 - nm0), al1 = __expf(m1 - nm1);
        m0 = nm0; m1 = nm1;
        float ps0 = 0.f, ps1 = 0.f;
#pragma unroll
        for (int j = 0; j < 8; j++) {
            s[j][0] = __expf(s[j][0] - nm0);
            s[j][1] = __expf(s[j][1] - nm0);
            s[j][2] = __expf(s[j][2] - nm1);
            s[j][3] = __expf(s[j][3] - nm1);
            ps0 += s[j][0] + s[j][1];
            ps1 += s[j][2] + s[j][3];
        }
        ps0 += __shfl_xor_sync(0xffffffffu, ps0, 1);
        ps0 += __shfl_xor_sync(0xffffffffu, ps0, 2);
        ps1 += __shfl_xor_sync(0xffffffffu, ps1, 1);
        ps1 += __shfl_xor_sync(0xffffffffu, ps1, 2);
        l0 = l0 * al0 + ps0;
        l1 = l1 * al1 + ps1;
#pragma unroll
        for (int j = 0; j < 8; j++) {
            o[j][0] *= al0; o[j][1] *= al0;
            o[j][2] *= al1; o[j][3] *= al1;
        }

        // ---- O += P V : P C-frags -> A-frags in registers ----
#pragma unroll
        for (int c = 0; c < 4; c++) {
            uint32_t ph[4], pl[4];
            ph[0] = pk_hilo(s[2 * c][0],     s[2 * c][1],     pl[0]);
            ph[1] = pk_hilo(s[2 * c][2],     s[2 * c][3],     pl[1]);
            ph[2] = pk_hilo(s[2 * c + 1][0], s[2 * c + 1][1], pl[2]);
            ph[3] = pk_hilo(s[2 * c + 1][2], s[2 * c + 1][3], pl[3]);

            uint32_t Vh_[4][4], Vl_[4][4];
#pragma unroll
            for (int g = 0; g < 4; g++) {
                LDM4(Vh_[g], sbase + AT_VH + ((uint32_t)c << 11) + bOff[g]);
            }
#pragma unroll
            for (int g = 0; g < 4; g++) {
                LDM4(Vl_[g], sbase + AT_VL + ((uint32_t)c << 11) + bOff[g]);
            }
#pragma unroll
            for (int j = 0; j < 8; j++) {
                const uint32_t* bg = Vh_[j >> 1] + ((j & 1) << 1);
                MMA_BF16(o[j], ph, bg[0], bg[1]);
            }
#pragma unroll
            for (int j = 0; j < 8; j++) {
                const uint32_t* bg = Vh_[j >> 1] + ((j & 1) << 1);
                MMA_BF16(o[j], pl, bg[0], bg[1]);
            }
#pragma unroll
            for (int j = 0; j < 8; j++) {
                const uint32_t* bg = Vl_[j >> 1] + ((j & 1) << 1);
                MMA_BF16(o[j], ph, bg[0], bg[1]);
            }
        }
    }

    // ---- per-head constants ----
    float bsig = 1.f / (1.f + expf(-beta_[h]));
    float sa, ca;
    sincosf(PI_F * bsig, &sa, &ca);
    float iv  = 1.f / (1.f + expf(-inval[h]));
    float ov  = 1.f / (1.f + expf(-outval[h]));
    float gch = tanhf(chiv[h]);
    float fac = iv * ov * gch;         // rotation is linear: fold into one factor

    // ---- normalize, rotate (frag pairs j, j+4 = cols +32), write out ----
    const float inv0 = 1.f / l0, inv1 = 1.f / l1;
    const int   fr   = lane >> 2;
    const int   fc   = (lane & 3) << 1;
    float* ob = out + ((size_t)(b * T_SEQ + q0 + wm + fr)) * DMODEL + h * DHEAD;
#pragma unroll
    for (int j = 0; j < 4; j++) {
        float xr0 = o[j][0] * inv0,     xr1 = o[j][1] * inv0;
        float xi0 = o[j + 4][0] * inv0, xi1 = o[j + 4][1] * inv0;
        *(float2*)(ob + 8 * j + fc) =
            make_float2((xr0 * ca - xi0 * sa) * fac, (xr1 * ca - xi1 * sa) * fac);
        *(float2*)(ob + 8 * j + fc + 32) =
            make_float2((xr0 * sa + xi0 * ca) * fac, (xr1 * sa + xi1 * ca) * fac);
        float yr0 = o[j][2] * inv1,     yr1 = o[j][3] * inv1;
        float yi0 = o[j + 4][2] * inv1, yi1 = o[j + 4][3] * inv1;
        *(float2*)(ob + 8 * DMODEL + 8 * j + fc) =
            make_float2((yr0 * ca - yi0 * sa) * fac, (yr1 * ca - yi1 * sa) * fac);
        *(float2*)(ob + 8 * DMODEL + 8 * j + fc + 32) =
            make_float2((yr0 * sa + yi0 * ca) * fac, (yr1 * sa + yi1 * ca) * fac);
    }
}

// =========================================================================
extern "C" void kernel_launch(void* const* d_in, const int* in_sizes, int n_in,
                              void* d_out, int out_size)
{
    (void)in_sizes; (void)n_in; (void)out_size;

    const float* x    = (const float*)d_in[0];
    const float* Wq   = (const float*)d_in[1];
    const float* Wk   = (const float*)d_in[2];
    const float* Wv   = (const float*)d_in[3];
    const float* We   = (const float*)d_in[4];
    const float* beta = (const float*)d_in[5];
    const float* ivv  = (const float*)d_in[6];
    const float* ovv  = (const float*)d_in[7];
    const float* chi  = (const float*)d_in[8];
    float* out = (float*)d_out;

    float *qp, *kp, *vp, *ap;
    cudaGetSymbolAddress((void**)&qp, g_q);
    cudaGetSymbolAddress((void**)&kp, g_k);
    cudaGetSymbolAddress((void**)&vp, g_v);
    cudaGetSymbolAddress((void**)&ap, g_ao);

    cudaFuncSetAttribute(attn_mma, cudaFuncAttributeMaxDynamicSharedMemorySize,
                         ATTN_SMEM);

    dim3 gqkv(DMODEL / 128, MROWS / 128, 3);   // fused Q/K/V projections
    gemm_bf16x3<<<gqkv, 256>>>(x, Wq, Wk, Wv, qp, kp, vp);

    dim3 ga(T_SEQ / 128, NHEADS, BATCH);       // (16, 16, 2)
    attn_mma<<<ga, 256, ATTN_SMEM>>>(qp, kp, vp, beta, ivv, ovv, chi, ap);

    dim3 go(DMODEL / 128, MROWS / 128, 1);     // output projection
    gemm_bf16x3<<<go, 256>>>(ap, We, We, We, out, out, out);
}

// round 14
// speedup vs baseline: 5.0441x; 1.2079x over previous
#include <cuda_runtime.h>
#include <cuda_bf16.h>
#include <math.h>
#include <stdint.h>

#define T_SEQ   2048
#define BATCH   2
#define DMODEL  1024
#define NHEADS  16
#define DHEAD   64
#define MROWS   (BATCH * T_SEQ)   // 4096
#define PI_F    3.14159265358979323846f

// ---------------- device scratch (no allocations allowed) ----------------
__device__ float g_q [MROWS * DMODEL];
__device__ float g_k [MROWS * DMODEL];
__device__ float g_v [MROWS * DMODEL];
__device__ float g_ao[MROWS * DMODEL];

// =========================================================================
// helpers
// =========================================================================
__device__ __forceinline__ uint32_t smem_u32(const void* p) {
    uint32_t a;
    asm("{ .reg .u64 t; cvta.to.shared.u64 t, %1; cvt.u32.u64 %0, t; }"
        : "=r"(a) : "l"(p));
    return a;
}

// swizzled byte offset of the 16B quad holding (row, half-of-16-k) in a
// [rows][16] bf16 chunk. The 8 rows of any ldmatrix 8x8 matrix (fixed half)
// hit 8 distinct 16B bank groups.
__device__ __forceinline__ uint32_t qoff(int row, int half) {
    return (uint32_t)((((row >> 3) << 4) + ((row & 7) << 1) +
                       (half ^ ((row >> 2) & 1))) << 4);
}

#define LDM4(r, addr) \
    asm volatile("ldmatrix.sync.aligned.m8n8.x4.shared.b16 {%0,%1,%2,%3}, [%4];" \
        : "=r"((r)[0]), "=r"((r)[1]), "=r"((r)[2]), "=r"((r)[3]) : "r"(addr))

#define MMA_BF16(d, a, b0_, b1_) \
    asm volatile("mma.sync.aligned.m16n8k16.row.col.f32.bf16.bf16.f32 " \
        "{%0,%1,%2,%3},{%4,%5,%6,%7},{%8,%9},{%0,%1,%2,%3};" \
        : "+f"((d)[0]), "+f"((d)[1]), "+f"((d)[2]), "+f"((d)[3]) \
        : "r"((a)[0]), "r"((a)[1]), "r"((a)[2]), "r"((a)[3]), \
          "r"(b0_), "r"(b1_))

// fp32x4 -> bf16 hi (rn) + bf16 lo (rn of residual), packed as uint2 (8B)
__device__ __forceinline__ void cvt_hilo(float4 v, uint2& hi, uint2& lo) {
    __nv_bfloat162 h01 = __floats2bfloat162_rn(v.x, v.y);
    __nv_bfloat162 h23 = __floats2bfloat162_rn(v.z, v.w);
    float2 f01 = __bfloat1622float2(h01);
    float2 f23 = __bfloat1622float2(h23);
    __nv_bfloat162 l01 = __floats2bfloat162_rn(v.x - f01.x, v.y - f01.y);
    __nv_bfloat162 l23 = __floats2bfloat162_rn(v.z - f23.x, v.w - f23.y);
    hi.x = *reinterpret_cast<unsigned*>(&h01);
    hi.y = *reinterpret_cast<unsigned*>(&h23);
    lo.x = *reinterpret_cast<unsigned*>(&l01);
    lo.y = *reinterpret_cast<unsigned*>(&l23);
}

// two fp32 -> packed bf16x2 hi + bf16x2 lo(residual)
__device__ __forceinline__ uint32_t pk_hilo(float a, float b, uint32_t& lo) {
    __nv_bfloat162 h = __floats2bfloat162_rn(a, b);
    float2 f = __bfloat1622float2(h);
    __nv_bfloat162 l = __floats2bfloat162_rn(a - f.x, b - f.y);
    lo = *reinterpret_cast<uint32_t*>(&l);
    return *reinterpret_cast<uint32_t*>(&h);
}

// =========================================================================
// bf16x3 mma.sync GEMM (NT), double-buffered pipeline:
// store chunk c+1 into buf^1 while MMAs consume buf; ONE barrier per chunk.
// =========================================================================
__global__ __launch_bounds__(256)
void gemm_bf16x3(const float* __restrict__ A,
                 const float* __restrict__ W0, const float* __restrict__ W1,
                 const float* __restrict__ W2,
                 float* __restrict__ C0, float* __restrict__ C1,
                 float* __restrict__ C2)
{
    __shared__ __align__(16) __nv_bfloat16 sAh[2][2048];
    __shared__ __align__(16) __nv_bfloat16 sAl[2][2048];
    __shared__ __align__(16) __nv_bfloat16 sBh[2][2048];
    __shared__ __align__(16) __nv_bfloat16 sBl[2][2048];

    const float* B = (blockIdx.z == 0) ? W0 : (blockIdx.z == 1) ? W1 : W2;
    float*       C = (blockIdx.z == 0) ? C0 : (blockIdx.z == 1) ? C1 : C2;

    const int tid  = threadIdx.x;
    const int warp = tid >> 5;
    const int lane = tid & 31;
    const int wm   = (warp & 3) << 5;
    const int wn   = (warp >> 2) << 6;
    const int bm   = blockIdx.y << 7;
    const int bn   = blockIdx.x << 7;

    const int row0 = tid >> 2;
    const int f4   = tid & 3;
    const uint32_t st0 = qoff(row0,      f4 >> 1) + (uint32_t)((f4 & 1) << 3);
    const uint32_t st1 = qoff(row0 + 64, f4 >> 1) + (uint32_t)((f4 & 1) << 3);

    char* cAh = (char*)sAh; char* cAl = (char*)sAl;
    char* cBh = (char*)sBh; char* cBl = (char*)sBl;

    const uint32_t bAh = smem_u32(sAh), bAl = smem_u32(sAl);
    const uint32_t bBh = smem_u32(sBh), bBl = smem_u32(sBl);
    uint32_t aOff[2], bOff[4];
    {
        int r  = (lane & 7) + ((lane >> 3) & 1) * 8;
        int hA = (lane >> 4) & 1;
        aOff[0] = qoff(wm + r,      hA);
        aOff[1] = qoff(wm + 16 + r, hA);
        int rn_ = (lane & 7) + ((lane >> 4) & 1) * 8;
        int hB  = (lane >> 3) & 1;
#pragma unroll
        for (int j = 0; j < 4; j++)
            bOff[j] = qoff(wn + 16 * j + rn_, hB);
    }

    float acc[2][8][4];
#pragma unroll
    for (int i = 0; i < 2; i++)
#pragma unroll
        for (int j = 0; j < 8; j++)
#pragma unroll
            for (int e = 0; e < 4; e++) acc[i][j][e] = 0.f;

    const float* pA = A + (size_t)(bm + row0) * DMODEL + f4 * 4;
    const float* pB = B + (size_t)(bn + row0) * DMODEL + f4 * 4;

    // ---- stage chunk 0 into buf 0 ----
    {
        float4 ra0 = *(const float4*)pA;
        float4 ra1 = *(const float4*)(pA + 64 * DMODEL);
        float4 rb0 = *(const float4*)pB;
        float4 rb1 = *(const float4*)(pB + 64 * DMODEL);
        uint2 hi, lo;
        cvt_hilo(ra0, hi, lo);
        *(uint2*)(cAh + st0) = hi; *(uint2*)(cAl + st0) = lo;
        cvt_hilo(ra1, hi, lo);
        *(uint2*)(cAh + st1) = hi; *(uint2*)(cAl + st1) = lo;
        cvt_hilo(rb0, hi, lo);
        *(uint2*)(cBh + st0) = hi; *(uint2*)(cBl + st0) = lo;
        cvt_hilo(rb1, hi, lo);
        *(uint2*)(cBh + st1) = hi; *(uint2*)(cBl + st1) = lo;
    }
    __syncthreads();

    for (int c = 0; c < DMODEL / 16; c++) {
        const uint32_t bo = (uint32_t)(c & 1) << 12;   // current buffer
        const uint32_t so = bo ^ 4096u;                // staging buffer

        // ---- prefetch chunk c+1 (long-latency, overlaps MMA below) ----
        float4 ra0, ra1, rb0, rb1;
        if (c < DMODEL / 16 - 1) {
            pA += 16; pB += 16;
            ra0 = *(const float4*)pA;
            ra1 = *(const float4*)(pA + 64 * DMODEL);
            rb0 = *(const float4*)pB;
            rb1 = *(const float4*)(pB + 64 * DMODEL);
        }

        // ---- MMA on current buffer ----
        uint32_t Ah[2][4], Al[2][4], Bh[4][4], Bl[4][4];
        LDM4(Ah[0], bAh + bo + aOff[0]);  LDM4(Ah[1], bAh + bo + aOff[1]);
        LDM4(Al[0], bAl + bo + aOff[0]);  LDM4(Al[1], bAl + bo + aOff[1]);
#pragma unroll
        for (int g = 0; g < 4; g++) { LDM4(Bh[g], bBh + bo + bOff[g]); }
#pragma unroll
        for (int g = 0; g < 4; g++) { LDM4(Bl[g], bBl + bo + bOff[g]); }

#pragma unroll
        for (int i = 0; i < 2; i++)
#pragma unroll
            for (int j = 0; j < 8; j++) {
                const uint32_t* bg = Bh[j >> 1] + ((j & 1) << 1);
                MMA_BF16(acc[i][j], Ah[i], bg[0], bg[1]);
            }
#pragma unroll
        for (int i = 0; i < 2; i++)
#pragma unroll
            for (int j = 0; j < 8; j++) {
                const uint32_t* bg = Bh[j >> 1] + ((j & 1) << 1);
                MMA_BF16(acc[i][j], Al[i], bg[0], bg[1]);
            }
#pragma unroll
        for (int i = 0; i < 2; i++)
#pragma unroll
            for (int j = 0; j < 8; j++) {
                const uint32_t* bg = Bl[j >> 1] + ((j & 1) << 1);
                MMA_BF16(acc[i][j], Ah[i], bg[0], bg[1]);
            }

        // ---- stage chunk c+1 into the other buffer ----
        if (c < DMODEL / 16 - 1) {
            uint2 hi, lo;
            cvt_hilo(ra0, hi, lo);
            *(uint2*)(cAh + so + st0) = hi; *(uint2*)(cAl + so + st0) = lo;
            cvt_hilo(ra1, hi, lo);
            *(uint2*)(cAh + so + st1) = hi; *(uint2*)(cAl + so + st1) = lo;
            cvt_hilo(rb0, hi, lo);
            *(uint2*)(cBh + so + st0) = hi; *(uint2*)(cBl + so + st0) = lo;
            cvt_hilo(rb1, hi, lo);
            *(uint2*)(cBh + so + st1) = hi; *(uint2*)(cBl + so + st1) = lo;
        }
        __syncthreads();
    }

    const int fr = lane >> 2;
    const int fc = (lane & 3) << 1;
#pragma unroll
    for (int i = 0; i < 2; i++) {
#pragma unroll
        for (int j = 0; j < 8; j++) {
            float* c0p = C + (size_t)(bm + wm + i * 16 + fr) * DMODEL
                           + bn + wn + j * 8 + fc;
            *(float2*)c0p                 = make_float2(acc[i][j][0], acc[i][j][1]);
            *(float2*)(c0p + 8 * DMODEL)  = make_float2(acc[i][j][2], acc[i][j][3]);
        }
    }
}

// =========================================================================
// bf16x3 mma.sync flash attention + rotation/valve epilogue.
// Double-buffered K/V tiles: stage tile kt+1 while computing tile kt;
// ONE barrier per tile. Q frags register-resident. P re-packed in regs.
// =========================================================================
#define AT_QH 0
#define AT_QL 16384
#define AT_KV 32768        // base of double-buffered K/V region
#define KV_STRIDE 32768    // per-buffer: KH 0 | KL 8192 | VH 16384 | VL 24576
#define ATTN_SMEM (32768 + 2 * KV_STRIDE)   // 98,304 B

__global__ __launch_bounds__(256)
void attn_mma(const float* __restrict__ Q, const float* __restrict__ Kg,
              const float* __restrict__ Vg,
              const float* __restrict__ beta_, const float* __restrict__ inval,
              const float* __restrict__ outval, const float* __restrict__ chiv,
              float* __restrict__ out)
{
    extern __shared__ __align__(16) char smb[];

    const int h    = blockIdx.y;
    const int b    = blockIdx.z;
    const int q0   = blockIdx.x << 7;
    const int tid  = threadIdx.x;
    const int warp = tid >> 5;
    const int lane = tid & 31;
    const int wm   = warp << 4;

    const float* qb = Q  + ((size_t)(b * T_SEQ + q0)) * DMODEL + h * DHEAD;
    const float* kb = Kg + ((size_t)(b * T_SEQ))      * DMODEL + h * DHEAD;
    const float* vb = Vg + ((size_t)(b * T_SEQ))      * DMODEL + h * DHEAD;

    // per-thread staging geometry (K and V loads share the f/row/q4 map)
    const int srow = tid >> 4;            // +64 per i-step/4 pattern below
    const int sq4  = tid & 15;

    // ---- stage Q (pre-scaled 0.125) hi/lo: 4 chunks of [128][16] ----
#pragma unroll
    for (int i = 0; i < 8; i++) {
        int f   = tid + (i << 8);
        int row = f >> 4;
        int q4  = f & 15;
        float4 v = *(const float4*)(qb + (size_t)row * DMODEL + (q4 << 2));
        v.x *= 0.125f; v.y *= 0.125f; v.z *= 0.125f; v.w *= 0.125f;
        uint2 hi, lo;
        cvt_hilo(v, hi, lo);
        uint32_t off = ((uint32_t)(q4 >> 2) << 12) + qoff(row, (q4 >> 1) & 1)
                     + ((uint32_t)(q4 & 1) << 3);
        *(uint2*)(smb + AT_QH + off) = hi;
        *(uint2*)(smb + AT_QL + off) = lo;
    }

    // ---- stage K/V tile 0 into buffer 0 ----
    {
        const float* kbt = kb;
        const float* vbt = vb;
#pragma unroll
        for (int i = 0; i < 4; i++) {
            int row = srow + (i << 4);     // 0..63
            float4 v = *(const float4*)(kbt + (size_t)row * DMODEL + (sq4 << 2));
            uint2 hi, lo;
            cvt_hilo(v, hi, lo);
            uint32_t off = ((uint32_t)(sq4 >> 2) << 11) + qoff(row, (sq4 >> 1) & 1)
                         + ((uint32_t)(sq4 & 1) << 3);
            *(uint2*)(smb + AT_KV + off) = hi;
            *(uint2*)(smb + AT_KV + 8192 + off) = lo;
        }
#pragma unroll
        for (int i = 0; i < 4; i++) {
            int key = srow + (i << 4);
            int dh0 = sq4 << 2;
            float4 v = *(const float4*)(vbt + (size_t)key * DMODEL + dh0);
            uint32_t cb  = ((uint32_t)(key >> 4) << 11);
            int      chf = (key >> 3) & 1;
            uint32_t el  = (uint32_t)((key & 7) << 1);
            float vv[4] = {v.x, v.y, v.z, v.w};
#pragma unroll
            for (int e = 0; e < 4; e++) {
                __nv_bfloat16 hv = __float2bfloat16(vv[e]);
                __nv_bfloat16 lv = __float2bfloat16(vv[e] - __bfloat162float(hv));
                uint32_t ad = cb + qoff(dh0 + e, chf) + el;
                *(__nv_bfloat16*)(smb + AT_KV + 16384 + ad) = hv;
                *(__nv_bfloat16*)(smb + AT_KV + 24576 + ad) = lv;
            }
        }
    }
    __syncthreads();

    // ---- fragment smem addresses ----
    const uint32_t sbase = smem_u32(smb);
    uint32_t aOffQ[4], bOff[4];
    {
        int r  = (lane & 7) + ((lane >> 3) & 1) * 8;
        int hA = (lane >> 4) & 1;
#pragma unroll
        for (int c = 0; c < 4; c++)
            aOffQ[c] = ((uint32_t)c << 12) + qoff(wm + r, hA);
        int rn_ = (lane & 7) + ((lane >> 4) & 1) * 8;
        int hB  = (lane >> 3) & 1;
#pragma unroll
        for (int g = 0; g < 4; g++)
            bOff[g] = qoff(16 * g + rn_, hB);
    }

    // ---- resident Q fragments ----
    uint32_t Qh[4][4], Ql[4][4];
#pragma unroll
    for (int c = 0; c < 4; c++) {
        LDM4(Qh[c], sbase + AT_QH + aOffQ[c]);
        LDM4(Ql[c], sbase + AT_QL + aOffQ[c]);
    }

    float o[8][4];
#pragma unroll
    for (int j = 0; j < 8; j++)
#pragma unroll
        for (int e = 0; e < 4; e++) o[j][e] = 0.f;
    float m0 = -1e30f, m1 = -1e30f, l0 = 0.f, l1 = 0.f;

    for (int kt = 0; kt < T_SEQ / 64; kt++) {
        const uint32_t bo = AT_KV + ((uint32_t)(kt & 1)) * KV_STRIDE;
        const uint32_t so = AT_KV + ((uint32_t)((kt & 1) ^ 1)) * KV_STRIDE;
        const bool pf = (kt < T_SEQ / 64 - 1);

        // ---- prefetch next tile's K/V (overlaps the MMA body) ----
        float4 kpre[4], vpre[4];
        if (pf) {
            const float* kbt = kb + (size_t)(kt + 1) * 64 * DMODEL;
            const float* vbt = vb + (size_t)(kt + 1) * 64 * DMODEL;
#pragma unroll
            for (int i = 0; i < 4; i++) {
                int row = srow + (i << 4);
                kpre[i] = *(const float4*)(kbt + (size_t)row * DMODEL + (sq4 << 2));
                vpre[i] = *(const float4*)(vbt + (size_t)row * DMODEL + (sq4 << 2));
            }
        }

        // ---- S = (Q/8) K^T ----
        float s[8][4];
#pragma unroll
        for (int j = 0; j < 8; j++)
#pragma unroll
            for (int e = 0; e < 4; e++) s[j][e] = 0.f;

#pragma unroll
        for (int c = 0; c < 4; c++) {
            uint32_t Kh_[4][4], Kl_[4][4];
#pragma unroll
            for (int g = 0; g < 4; g++) {
                LDM4(Kh_[g], sbase + bo + ((uint32_t)c << 11) + bOff[g]);
            }
#pragma unroll
            for (int g = 0; g < 4; g++) {
                LDM4(Kl_[g], sbase + bo + 8192 + ((uint32_t)c << 11) + bOff[g]);
            }
#pragma unroll
            for (int j = 0; j < 8; j++) {
                const uint32_t* bg = Kh_[j >> 1] + ((j & 1) << 1);
                MMA_BF16(s[j], Qh[c], bg[0], bg[1]);
            }
#pragma unroll
            for (int j = 0; j < 8; j++) {
                const uint32_t* bg = Kh_[j >> 1] + ((j & 1) << 1);
                MMA_BF16(s[j], Ql[c], bg[0], bg[1]);
            }
#pragma unroll
            for (int j = 0; j < 8; j++) {
                const uint32_t* bg = Kl_[j >> 1] + ((j & 1) << 1);
                MMA_BF16(s[j], Qh[c], bg[0], bg[1]);
            }
        }

        // ---- online softmax ----
        float mx0 = -1e30f, mx1 = -1e30f;
#pragma unroll
        for (int j = 0; j < 8; j++) {
            mx0 = fmaxf(mx0, fmaxf(s[j][0], s[j][1]));
            mx1 = fmaxf(mx1, fmaxf(s[j][2], s[j][3]));
        }
        mx0 = fmaxf(mx0, __shfl_xor_sync(0xffffffffu, mx0, 1));
        mx0 = fmaxf(mx0, __shfl_xor_sync(0xffffffffu, mx0, 2));
        mx1 = fmaxf(mx1, __shfl_xor_sync(0xffffffffu, mx1, 1));
        mx1 = fmaxf(mx1, __shfl_xor_sync(0xffffffffu, mx1, 2));
        float nm0 = fmaxf(m0, mx0), nm1 = fmaxf(m1, mx1);
        float al0 = __expf(m0 - nm0), al1 = __expf(m1 - nm1);
        m0 = nm0; m1 = nm1;
        float ps0 = 0.f, ps1 = 0.f;
#pragma unroll
        for (int j = 0; j < 8; j++) {
            s[j][0] = __expf(s[j][0] - nm0);
            s[j][1] = __expf(s[j][1] - nm0);
            s[j][2] = __expf(s[j][2] - nm1);
            s[j][3] = __expf(s[j][3] - nm1);
            ps0 += s[j][0] + s[j][1];
            ps1 += s[j][2] + s[j][3];
        }
        ps0 += __shfl_xor_sync(0xffffffffu, ps0, 1);
        ps0 += __shfl_xor_sync(0xffffffffu, ps0, 2);
        ps1 += __shfl_xor_sync(0xffffffffu, ps1, 1);
        ps1 += __shfl_xor_sync(0xffffffffu, ps1, 2);
        l0 = l0 * al0 + ps0;
        l1 = l1 * al1 + ps1;
#pragma unroll
        for (int j = 0; j < 8; j++) {
            o[j][0] *= al0; o[j][1] *= al0;
            o[j][2] *= al1; o[j][3] *= al1;
        }

        // ---- O += P V ----
#pragma unroll
        for (int c = 0; c < 4; c++) {
            uint32_t ph[4], pl[4];
            ph[0] = pk_hilo(s[2 * c][0],     s[2 * c][1],     pl[0]);
            ph[1] = pk_hilo(s[2 * c][2],     s[2 * c][3],     pl[1]);
            ph[2] = pk_hilo(s[2 * c + 1][0], s[2 * c + 1][1], pl[2]);
            ph[3] = pk_hilo(s[2 * c + 1][2], s[2 * c + 1][3], pl[3]);

            uint32_t Vh_[4][4], Vl_[4][4];
#pragma unroll
            for (int g = 0; g < 4; g++) {
                LDM4(Vh_[g], sbase + bo + 16384 + ((uint32_t)c << 11) + bOff[g]);
            }
#pragma unroll
            for (int g = 0; g < 4; g++) {
                LDM4(Vl_[g], sbase + bo + 24576 + ((uint32_t)c << 11) + bOff[g]);
            }
#pragma unroll
            for (int j = 0; j < 8; j++) {
                const uint32_t* bg = Vh_[j >> 1] + ((j & 1) << 1);
                MMA_BF16(o[j], ph, bg[0], bg[1]);
            }
#pragma unroll
            for (int j = 0; j < 8; j++) {
                const uint32_t* bg = Vh_[j >> 1] + ((j & 1) << 1);
                MMA_BF16(o[j], pl, bg[0], bg[1]);
            }
#pragma unroll
            for (int j = 0; j < 8; j++) {
                const uint32_t* bg = Vl_[j >> 1] + ((j & 1) << 1);
                MMA_BF16(o[j], ph, bg[0], bg[1]);
            }
        }

        // ---- stage prefetched tile kt+1 into the other buffer ----
        if (pf) {
#pragma unroll
            for (int i = 0; i < 4; i++) {
                int row = srow + (i << 4);
                uint2 hi, lo;
                cvt_hilo(kpre[i], hi, lo);
                uint32_t off = ((uint32_t)(sq4 >> 2) << 11)
                             + qoff(row, (sq4 >> 1) & 1)
                             + ((uint32_t)(sq4 & 1) << 3);
                *(uint2*)(smb + so + off) = hi;
                *(uint2*)(smb + so + 8192 + off) = lo;
            }
#pragma unroll
            for (int i = 0; i < 4; i++) {
                int key = srow + (i << 4);
                int dh0 = sq4 << 2;
                uint32_t cb  = ((uint32_t)(key >> 4) << 11);
                int      chf = (key >> 3) & 1;
                uint32_t el  = (uint32_t)((key & 7) << 1);
                float vv[4] = {vpre[i].x, vpre[i].y, vpre[i].z, vpre[i].w};
#pragma unroll
                for (int e = 0; e < 4; e++) {
                    __nv_bfloat16 hv = __float2bfloat16(vv[e]);
                    __nv_bfloat16 lv = __float2bfloat16(vv[e] - __bfloat162float(hv));
                    uint32_t ad = cb + qoff(dh0 + e, chf) + el;
                    *(__nv_bfloat16*)(smb + so + 16384 + ad) = hv;
                    *(__nv_bfloat16*)(smb + so + 24576 + ad) = lv;
                }
            }
        }
        __syncthreads();
    }

    // ---- per-head constants ----
    float bsig = 1.f / (1.f + expf(-beta_[h]));
    float sa, ca;
    sincosf(PI_F * bsig, &sa, &ca);
    float iv  = 1.f / (1.f + expf(-inval[h]));
    float ov  = 1.f / (1.f + expf(-outval[h]));
    float gch = tanhf(chiv[h]);
    float fac = iv * ov * gch;

    // ---- normalize, rotate (frag pairs j, j+4 = cols +32), write out ----
    const float inv0 = 1.f / l0, inv1 = 1.f / l1;
    const int   fr   = lane >> 2;
    const int   fc   = (lane & 3) << 1;
    float* ob = out + ((size_t)(b * T_SEQ + q0 + wm + fr)) * DMODEL + h * DHEAD;
#pragma unroll
    for (int j = 0; j < 4; j++) {
        float xr0 = o[j][0] * inv0,     xr1 = o[j][1] * inv0;
        float xi0 = o[j + 4][0] * inv0, xi1 = o[j + 4][1] * inv0;
        *(float2*)(ob + 8 * j + fc) =
            make_float2((xr0 * ca - xi0 * sa) * fac, (xr1 * ca - xi1 * sa) * fac);
        *(float2*)(ob + 8 * j + fc + 32) =
            make_float2((xr0 * sa + xi0 * ca) * fac, (xr1 * sa + xi1 * ca) * fac);
        float yr0 = o[j][2] * inv1,     yr1 = o[j][3] * inv1;
        float yi0 = o[j + 4][2] * inv1, yi1 = o[j + 4][3] * inv1;
        *(float2*)(ob + 8 * DMODEL + 8 * j + fc) =
            make_float2((yr0 * ca - yi0 * sa) * fac, (yr1 * ca - yi1 * sa) * fac);
        *(float2*)(ob + 8 * DMODEL + 8 * j + fc + 32) =
            make_float2((yr0 * sa + yi0 * ca) * fac, (yr1 * sa + yi1 * ca) * fac);
    }
}

// =========================================================================
extern "C" void kernel_launch(void* const* d_in, const int* in_sizes, int n_in,
                              void* d_out, int out_size)
{
    (void)in_sizes; (void)n_in; (void)out_size;

    const float* x    = (const float*)d_in[0];
    const float* Wq   = (const float*)d_in[1];
    const float* Wk   = (const float*)d_in[2];
    const float* Wv   = (const float*)d_in[3];
    const float* We   = (const float*)d_in[4];
    const float* beta = (const float*)d_in[5];
    const float* ivv  = (const float*)d_in[6];
    const float* ovv  = (const float*)d_in[7];
    const float* chi  = (const float*)d_in[8];
    float* out = (float*)d_out;

    float *qp, *kp, *vp, *ap;
    cudaGetSymbolAddress((void**)&qp, g_q);
    cudaGetSymbolAddress((void**)&kp, g_k);
    cudaGetSymbolAddress((void**)&vp, g_v);
    cudaGetSymbolAddress((void**)&ap, g_ao);

    cudaFuncSetAttribute(attn_mma, cudaFuncAttributeMaxDynamicSharedMemorySize,
                         ATTN_SMEM);

    dim3 gqkv(DMODEL / 128, MROWS / 128, 3);   // fused Q/K/V projections
    gemm_bf16x3<<<gqkv, 256>>>(x, Wq, Wk, Wv, qp, kp, vp);

    dim3 ga(T_SEQ / 128, NHEADS, BATCH);       // (16, 16, 2)
    attn_mma<<<ga, 256, ATTN_SMEM>>>(qp, kp, vp, beta, ivv, ovv, chi, ap);

    dim3 go(DMODEL / 128, MROWS / 128, 1);     // output projection
    gemm_bf16x3<<<go, 256>>>(ap, We, We, We, out, out, out);
}

// round 15
// speedup vs baseline: 7.5218x; 1.4912x over previous
#include <cuda_runtime.h>
#include <cuda_fp16.h>
#include <math.h>
#include <stdint.h>

#define T_SEQ   2048
#define BATCH   2
#define DMODEL  1024
#define NHEADS  16
#define DHEAD   64
#define MROWS   (BATCH * T_SEQ)   // 4096
#define PI_F    3.14159265358979323846f

// ---------------- device scratch (no allocations allowed) ----------------
__device__ float g_q [MROWS * DMODEL];
__device__ float g_k [MROWS * DMODEL];
__device__ float g_v [MROWS * DMODEL];
__device__ float g_ao[MROWS * DMODEL];

// =========================================================================
// helpers
// =========================================================================
__device__ __forceinline__ uint32_t smem_u32(const void* p) {
    uint32_t a;
    asm("{ .reg .u64 t; cvta.to.shared.u64 t, %1; cvt.u32.u64 %0, t; }"
        : "=r"(a) : "l"(p));
    return a;
}

// swizzled byte offset of the 16B quad holding (row, half-of-16-k) in a
// [rows][16] fp16 chunk. The 8 rows of any ldmatrix 8x8 matrix (fixed half)
// hit 8 distinct 16B bank groups.
__device__ __forceinline__ uint32_t qoff(int row, int half) {
    return (uint32_t)((((row >> 3) << 4) + ((row & 7) << 1) +
                       (half ^ ((row >> 2) & 1))) << 4);
}

#define LDM4(r, addr) \
    asm volatile("ldmatrix.sync.aligned.m8n8.x4.shared.b16 {%0,%1,%2,%3}, [%4];" \
        : "=r"((r)[0]), "=r"((r)[1]), "=r"((r)[2]), "=r"((r)[3]) : "r"(addr))

#define MMA_F16(d, a, b0_, b1_) \
    asm volatile("mma.sync.aligned.m16n8k16.row.col.f32.f16.f16.f32 " \
        "{%0,%1,%2,%3},{%4,%5,%6,%7},{%8,%9},{%0,%1,%2,%3};" \
        : "+f"((d)[0]), "+f"((d)[1]), "+f"((d)[2]), "+f"((d)[3]) \
        : "r"((a)[0]), "r"((a)[1]), "r"((a)[2]), "r"((a)[3]), \
          "r"(b0_), "r"(b1_))

// fp32x4 -> fp16 hi (rn) + fp16 lo (rn of residual), packed as uint2 (8B)
__device__ __forceinline__ void cvt_hilo(float4 v, uint2& hi, uint2& lo) {
    __half2 h01 = __floats2half2_rn(v.x, v.y);
    __half2 h23 = __floats2half2_rn(v.z, v.w);
    float2 f01 = __half22float2(h01);
    float2 f23 = __half22float2(h23);
    __half2 l01 = __floats2half2_rn(v.x - f01.x, v.y - f01.y);
    __half2 l23 = __floats2half2_rn(v.z - f23.x, v.w - f23.y);
    hi.x = *reinterpret_cast<unsigned*>(&h01);
    hi.y = *reinterpret_cast<unsigned*>(&h23);
    lo.x = *reinterpret_cast<unsigned*>(&l01);
    lo.y = *reinterpret_cast<unsigned*>(&l23);
}

// fp32x4 -> fp16 hi only, packed as uint2
__device__ __forceinline__ uint2 cvt_hi(float4 v) {
    __half2 h01 = __floats2half2_rn(v.x, v.y);
    __half2 h23 = __floats2half2_rn(v.z, v.w);
    uint2 hi;
    hi.x = *reinterpret_cast<unsigned*>(&h01);
    hi.y = *reinterpret_cast<unsigned*>(&h23);
    return hi;
}

// two fp32 -> packed fp16x2 hi + fp16x2 lo(residual)
__device__ __forceinline__ uint32_t pk_hilo(float a, float b, uint32_t& lo) {
    __half2 h = __floats2half2_rn(a, b);
    float2 f = __half22float2(h);
    __half2 l = __floats2half2_rn(a - f.x, b - f.y);
    lo = *reinterpret_cast<uint32_t*>(&l);
    return *reinterpret_cast<uint32_t*>(&h);
}

// =========================================================================
// fp16 2-term mma.sync GEMM (NT): C = Ah*Bh + Al*Bh  (B uncompensated,
// error ~1.4e-4 rel). Double-buffered, one barrier per 16-wide K chunk.
// =========================================================================
__global__ __launch_bounds__(256)
void gemm_f16x2(const float* __restrict__ A,
                const float* __restrict__ W0, const float* __restrict__ W1,
                const float* __restrict__ W2,
                float* __restrict__ C0, float* __restrict__ C1,
                float* __restrict__ C2)
{
    __shared__ __align__(16) __half sAh[2][2048];
    __shared__ __align__(16) __half sAl[2][2048];
    __shared__ __align__(16) __half sBh[2][2048];

    const float* B = (blockIdx.z == 0) ? W0 : (blockIdx.z == 1) ? W1 : W2;
    float*       C = (blockIdx.z == 0) ? C0 : (blockIdx.z == 1) ? C1 : C2;

    const int tid  = threadIdx.x;
    const int warp = tid >> 5;
    const int lane = tid & 31;
    const int wm   = (warp & 3) << 5;
    const int wn   = (warp >> 2) << 6;
    const int bm   = blockIdx.y << 7;
    const int bn   = blockIdx.x << 7;

    const int row0 = tid >> 2;
    const int f4   = tid & 3;
    const uint32_t st0 = qoff(row0,      f4 >> 1) + (uint32_t)((f4 & 1) << 3);
    const uint32_t st1 = qoff(row0 + 64, f4 >> 1) + (uint32_t)((f4 & 1) << 3);

    char* cAh = (char*)sAh; char* cAl = (char*)sAl; char* cBh = (char*)sBh;

    const uint32_t bAh = smem_u32(sAh), bAl = smem_u32(sAl), bBh = smem_u32(sBh);
    uint32_t aOff[2], bOff[4];
    {
        int r  = (lane & 7) + ((lane >> 3) & 1) * 8;
        int hA = (lane >> 4) & 1;
        aOff[0] = qoff(wm + r,      hA);
        aOff[1] = qoff(wm + 16 + r, hA);
        int rn_ = (lane & 7) + ((lane >> 4) & 1) * 8;
        int hB  = (lane >> 3) & 1;
#pragma unroll
        for (int j = 0; j < 4; j++)
            bOff[j] = qoff(wn + 16 * j + rn_, hB);
    }

    float acc[2][8][4];
#pragma unroll
    for (int i = 0; i < 2; i++)
#pragma unroll
        for (int j = 0; j < 8; j++)
#pragma unroll
            for (int e = 0; e < 4; e++) acc[i][j][e] = 0.f;

    const float* pA = A + (size_t)(bm + row0) * DMODEL + f4 * 4;
    const float* pB = B + (size_t)(bn + row0) * DMODEL + f4 * 4;

    // ---- stage chunk 0 into buf 0 ----
    {
        float4 ra0 = *(const float4*)pA;
        float4 ra1 = *(const float4*)(pA + 64 * DMODEL);
        float4 rb0 = *(const float4*)pB;
        float4 rb1 = *(const float4*)(pB + 64 * DMODEL);
        uint2 hi, lo;
        cvt_hilo(ra0, hi, lo);
        *(uint2*)(cAh + st0) = hi; *(uint2*)(cAl + st0) = lo;
        cvt_hilo(ra1, hi, lo);
        *(uint2*)(cAh + st1) = hi; *(uint2*)(cAl + st1) = lo;
        *(uint2*)(cBh + st0) = cvt_hi(rb0);
        *(uint2*)(cBh + st1) = cvt_hi(rb1);
    }
    __syncthreads();

    for (int c = 0; c < DMODEL / 16; c++) {
        const uint32_t bo = (uint32_t)(c & 1) << 12;   // current buffer
        const uint32_t so = bo ^ 4096u;                // staging buffer

        // ---- prefetch chunk c+1 (overlaps MMA below) ----
        float4 ra0, ra1, rb0, rb1;
        if (c < DMODEL / 16 - 1) {
            pA += 16; pB += 16;
            ra0 = *(const float4*)pA;
            ra1 = *(const float4*)(pA + 64 * DMODEL);
            rb0 = *(const float4*)pB;
            rb1 = *(const float4*)(pB + 64 * DMODEL);
        }

        // ---- MMA on current buffer ----
        uint32_t Ah[2][4], Al[2][4], Bh[4][4];
        LDM4(Ah[0], bAh + bo + aOff[0]);  LDM4(Ah[1], bAh + bo + aOff[1]);
        LDM4(Al[0], bAl + bo + aOff[0]);  LDM4(Al[1], bAl + bo + aOff[1]);
#pragma unroll
        for (int g = 0; g < 4; g++) { LDM4(Bh[g], bBh + bo + bOff[g]); }

#pragma unroll
        for (int i = 0; i < 2; i++)
#pragma unroll
            for (int j = 0; j < 8; j++) {
                const uint32_t* bg = Bh[j >> 1] + ((j & 1) << 1);
                MMA_F16(acc[i][j], Ah[i], bg[0], bg[1]);
            }
#pragma unroll
        for (int i = 0; i < 2; i++)
#pragma unroll
            for (int j = 0; j < 8; j++) {
                const uint32_t* bg = Bh[j >> 1] + ((j & 1) << 1);
                MMA_F16(acc[i][j], Al[i], bg[0], bg[1]);
            }

        // ---- stage chunk c+1 into the other buffer ----
        if (c < DMODEL / 16 - 1) {
            uint2 hi, lo;
            cvt_hilo(ra0, hi, lo);
            *(uint2*)(cAh + so + st0) = hi; *(uint2*)(cAl + so + st0) = lo;
            cvt_hilo(ra1, hi, lo);
            *(uint2*)(cAh + so + st1) = hi; *(uint2*)(cAl + so + st1) = lo;
            *(uint2*)(cBh + so + st0) = cvt_hi(rb0);
            *(uint2*)(cBh + so + st1) = cvt_hi(rb1);
        }
        __syncthreads();
    }

    const int fr = lane >> 2;
    const int fc = (lane & 3) << 1;
#pragma unroll
    for (int i = 0; i < 2; i++) {
#pragma unroll
        for (int j = 0; j < 8; j++) {
            float* c0p = C + (size_t)(bm + wm + i * 16 + fr) * DMODEL
                           + bn + wn + j * 8 + fc;
            *(float2*)c0p                 = make_float2(acc[i][j][0], acc[i][j][1]);
            *(float2*)(c0p + 8 * DMODEL)  = make_float2(acc[i][j][2], acc[i][j][3]);
        }
    }
}

// =========================================================================
// fp16 2-term mma.sync flash attention + rotation/valve epilogue.
// S = Qh*Kh + Ql*Kh  (K uncompensated); O = Ph*Vh + Pl*Vh (V uncompensated).
// K/V staging + ldmatrix traffic HALVED vs bf16x3. Double-buffered tiles.
// =========================================================================
#define AT_QH 0
#define AT_QL 16384
#define AT_KV 32768        // base of double-buffered K/V region
#define KV_STRIDE 16384    // per-buffer: KH 0 | VH 8192
#define ATTN_SMEM (32768 + 2 * KV_STRIDE)   // 65,536 B

__global__ __launch_bounds__(256)
void attn_mma(const float* __restrict__ Q, const float* __restrict__ Kg,
              const float* __restrict__ Vg,
              const float* __restrict__ beta_, const float* __restrict__ inval,
              const float* __restrict__ outval, const float* __restrict__ chiv,
              float* __restrict__ out)
{
    extern __shared__ __align__(16) char smb[];

    const int h    = blockIdx.y;
    const int b    = blockIdx.z;
    const int q0   = blockIdx.x << 7;
    const int tid  = threadIdx.x;
    const int warp = tid >> 5;
    const int lane = tid & 31;
    const int wm   = warp << 4;

    const float* qb = Q  + ((size_t)(b * T_SEQ + q0)) * DMODEL + h * DHEAD;
    const float* kb = Kg + ((size_t)(b * T_SEQ))      * DMODEL + h * DHEAD;
    const float* vb = Vg + ((size_t)(b * T_SEQ))      * DMODEL + h * DHEAD;

    const int srow = tid >> 4;            // staging row base, +16 per i
    const int sq4  = tid & 15;

    // ---- stage Q (pre-scaled 0.125) hi/lo: 4 chunks of [128][16] ----
#pragma unroll
    for (int i = 0; i < 8; i++) {
        int f   = tid + (i << 8);
        int row = f >> 4;
        int q4  = f & 15;
        float4 v = *(const float4*)(qb + (size_t)row * DMODEL + (q4 << 2));
        v.x *= 0.125f; v.y *= 0.125f; v.z *= 0.125f; v.w *= 0.125f;
        uint2 hi, lo;
        cvt_hilo(v, hi, lo);
        uint32_t off = ((uint32_t)(q4 >> 2) << 12) + qoff(row, (q4 >> 1) & 1)
                     + ((uint32_t)(q4 & 1) << 3);
        *(uint2*)(smb + AT_QH + off) = hi;
        *(uint2*)(smb + AT_QL + off) = lo;
    }

    // ---- stage K/V tile 0 into buffer 0 (hi only) ----
    {
#pragma unroll
        for (int i = 0; i < 4; i++) {
            int row = srow + (i << 4);
            float4 v = *(const float4*)(kb + (size_t)row * DMODEL + (sq4 << 2));
            uint32_t off = ((uint32_t)(sq4 >> 2) << 11) + qoff(row, (sq4 >> 1) & 1)
                         + ((uint32_t)(sq4 & 1) << 3);
            *(uint2*)(smb + AT_KV + off) = cvt_hi(v);
        }
#pragma unroll
        for (int i = 0; i < 4; i++) {
            int key = srow + (i << 4);
            int dh0 = sq4 << 2;
            float4 v = *(const float4*)(vb + (size_t)key * DMODEL + dh0);
            uint32_t cb  = ((uint32_t)(key >> 4) << 11);
            int      chf = (key >> 3) & 1;
            uint32_t el  = (uint32_t)((key & 7) << 1);
            float vv[4] = {v.x, v.y, v.z, v.w};
#pragma unroll
            for (int e = 0; e < 4; e++) {
                uint32_t ad = cb + qoff(dh0 + e, chf) + el;
                *(__half*)(smb + AT_KV + 8192 + ad) = __float2half(vv[e]);
            }
        }
    }
    __syncthreads();

    // ---- fragment smem addresses ----
    const uint32_t sbase = smem_u32(smb);
    uint32_t aOffQ[4], bOff[4];
    {
        int r  = (lane & 7) + ((lane >> 3) & 1) * 8;
        int hA = (lane >> 4) & 1;
#pragma unroll
        for (int c = 0; c < 4; c++)
            aOffQ[c] = ((uint32_t)c << 12) + qoff(wm + r, hA);
        int rn_ = (lane & 7) + ((lane >> 4) & 1) * 8;
        int hB  = (lane >> 3) & 1;
#pragma unroll
        for (int g = 0; g < 4; g++)
            bOff[g] = qoff(16 * g + rn_, hB);
    }

    // ---- resident Q fragments ----
    uint32_t Qh[4][4], Ql[4][4];
#pragma unroll
    for (int c = 0; c < 4; c++) {
        LDM4(Qh[c], sbase + AT_QH + aOffQ[c]);
        LDM4(Ql[c], sbase + AT_QL + aOffQ[c]);
    }

    float o[8][4];
#pragma unroll
    for (int j = 0; j < 8; j++)
#pragma unroll
        for (int e = 0; e < 4; e++) o[j][e] = 0.f;
    float m0 = -1e30f, m1 = -1e30f, l0 = 0.f, l1 = 0.f;

    for (int kt = 0; kt < T_SEQ / 64; kt++) {
        const uint32_t bo = AT_KV + ((uint32_t)(kt & 1)) * KV_STRIDE;
        const uint32_t so = AT_KV + ((uint32_t)((kt & 1) ^ 1)) * KV_STRIDE;
        const bool pf = (kt < T_SEQ / 64 - 1);

        // ---- prefetch next tile's K/V (overlaps MMA body) ----
        float4 kpre[4], vpre[4];
        if (pf) {
            const float* kbt = kb + (size_t)(kt + 1) * 64 * DMODEL;
            const float* vbt = vb + (size_t)(kt + 1) * 64 * DMODEL;
#pragma unroll
            for (int i = 0; i < 4; i++) {
                int row = srow + (i << 4);
                kpre[i] = *(const float4*)(kbt + (size_t)row * DMODEL + (sq4 << 2));
                vpre[i] = *(const float4*)(vbt + (size_t)row * DMODEL + (sq4 << 2));
            }
        }

        // ---- S = (Q/8) K^T ----
        float s[8][4];
#pragma unroll
        for (int j = 0; j < 8; j++)
#pragma unroll
            for (int e = 0; e < 4; e++) s[j][e] = 0.f;

#pragma unroll
        for (int c = 0; c < 4; c++) {
            uint32_t Kh_[4][4];
#pragma unroll
            for (int g = 0; g < 4; g++) {
                LDM4(Kh_[g], sbase + bo + ((uint32_t)c << 11) + bOff[g]);
            }
#pragma unroll
            for (int j = 0; j < 8; j++) {
                const uint32_t* bg = Kh_[j >> 1] + ((j & 1) << 1);
                MMA_F16(s[j], Qh[c], bg[0], bg[1]);
            }
#pragma unroll
            for (int j = 0; j < 8; j++) {
                const uint32_t* bg = Kh_[j >> 1] + ((j & 1) << 1);
                MMA_F16(s[j], Ql[c], bg[0], bg[1]);
            }
        }

        // ---- online softmax ----
        float mx0 = -1e30f, mx1 = -1e30f;
#pragma unroll
        for (int j = 0; j < 8; j++) {
            mx0 = fmaxf(mx0, fmaxf(s[j][0], s[j][1]));
            mx1 = fmaxf(mx1, fmaxf(s[j][2], s[j][3]));
        }
        mx0 = fmaxf(mx0, __shfl_xor_sync(0xffffffffu, mx0, 1));
        mx0 = fmaxf(mx0, __shfl_xor_sync(0xffffffffu, mx0, 2));
        mx1 = fmaxf(mx1, __shfl_xor_sync(0xffffffffu, mx1, 1));
        mx1 = fmaxf(mx1, __shfl_xor_sync(0xffffffffu, mx1, 2));
        float nm0 = fmaxf(m0, mx0), nm1 = fmaxf(m1, mx1);
        float al0 = __expf(m0 - nm0), al1 = __expf(m1 - nm1);
        m0 = nm0; m1 = nm1;
        float ps0 = 0.f, ps1 = 0.f;
#pragma unroll
        for (int j = 0; j < 8; j++) {
            s[j][0] = __expf(s[j][0] - nm0);
            s[j][1] = __expf(s[j][1] - nm0);
            s[j][2] = __expf(s[j][2] - nm1);
            s[j][3] = __expf(s[j][3] - nm1);
            ps0 += s[j][0] + s[j][1];
            ps1 += s[j][2] + s[j][3];
        }
        ps0 += __shfl_xor_sync(0xffffffffu, ps0, 1);
        ps0 += __shfl_xor_sync(0xffffffffu, ps0, 2);
        ps1 += __shfl_xor_sync(0xffffffffu, ps1, 1);
        ps1 += __shfl_xor_sync(0xffffffffu, ps1, 2);
        l0 = l0 * al0 + ps0;
        l1 = l1 * al1 + ps1;
#pragma unroll
        for (int j = 0; j < 8; j++) {
            o[j][0] *= al0; o[j][1] *= al0;
            o[j][2] *= al1; o[j][3] *= al1;
        }

        // ---- O += P V ----
#pragma unroll
        for (int c = 0; c < 4; c++) {
            uint32_t ph[4], pl[4];
            ph[0] = pk_hilo(s[2 * c][0],     s[2 * c][1],     pl[0]);
            ph[1] = pk_hilo(s[2 * c][2],     s[2 * c][3],     pl[1]);
            ph[2] = pk_hilo(s[2 * c + 1][0], s[2 * c + 1][1], pl[2]);
            ph[3] = pk_hilo(s[2 * c + 1][2], s[2 * c + 1][3], pl[3]);

            uint32_t Vh_[4][4];
#pragma unroll
            for (int g = 0; g < 4; g++) {
                LDM4(Vh_[g], sbase + bo + 8192 + ((uint32_t)c << 11) + bOff[g]);
            }
#pragma unroll
            for (int j = 0; j < 8; j++) {
                const uint32_t* bg = Vh_[j >> 1] + ((j & 1) << 1);
                MMA_F16(o[j], ph, bg[0], bg[1]);
            }
#pragma unroll
            for (int j = 0; j < 8; j++) {
                const uint32_t* bg = Vh_[j >> 1] + ((j & 1) << 1);
                MMA_F16(o[j], pl, bg[0], bg[1]);
            }
        }

        // ---- stage prefetched tile kt+1 into the other buffer ----
        if (pf) {
#pragma unroll
            for (int i = 0; i < 4; i++) {
                int row = srow + (i << 4);
                uint32_t off = ((uint32_t)(sq4 >> 2) << 11)
                             + qoff(row, (sq4 >> 1) & 1)
                             + ((uint32_t)(sq4 & 1) << 3);
                *(uint2*)(smb + so + off) = cvt_hi(kpre[i]);
            }
#pragma unroll
            for (int i = 0; i < 4; i++) {
                int key = srow + (i << 4);
                int dh0 = sq4 << 2;
                uint32_t cb  = ((uint32_t)(key >> 4) << 11);
                int      chf = (key >> 3) & 1;
                uint32_t el  = (uint32_t)((key & 7) << 1);
                float vv[4] = {vpre[i].x, vpre[i].y, vpre[i].z, vpre[i].w};
#pragma unroll
                for (int e = 0; e < 4; e++) {
                    uint32_t ad = cb + qoff(dh0 + e, chf) + el;
                    *(__half*)(smb + so + 8192 + ad) = __float2half(vv[e]);
                }
            }
        }
        __syncthreads();
    }

    // ---- per-head constants ----
    float bsig = 1.f / (1.f + expf(-beta_[h]));
    float sa, ca;
    sincosf(PI_F * bsig, &sa, &ca);
    float iv  = 1.f / (1.f + expf(-inval[h]));
    float ov  = 1.f / (1.f + expf(-outval[h]));
    float gch = tanhf(chiv[h]);
    float fac = iv * ov * gch;

    // ---- normalize, rotate (frag pairs j, j+4 = cols +32), write out ----
    const float inv0 = 1.f / l0, inv1 = 1.f / l1;
    const int   fr   = lane >> 2;
    const int   fc   = (lane & 3) << 1;
    float* ob = out + ((size_t)(b * T_SEQ + q0 + wm + fr)) * DMODEL + h * DHEAD;
#pragma unroll
    for (int j = 0; j < 4; j++) {
        float xr0 = o[j][0] * inv0,     xr1 = o[j][1] * inv0;
        float xi0 = o[j + 4][0] * inv0, xi1 = o[j + 4][1] * inv0;
        *(float2*)(ob + 8 * j + fc) =
            make_float2((xr0 * ca - xi0 * sa) * fac, (xr1 * ca - xi1 * sa) * fac);
        *(float2*)(ob + 8 * j + fc + 32) =
            make_float2((xr0 * sa + xi0 * ca) * fac, (xr1 * sa + xi1 * ca) * fac);
        float yr0 = o[j][2] * inv1,     yr1 = o[j][3] * inv1;
        float yi0 = o[j + 4][2] * inv1, yi1 = o[j + 4][3] * inv1;
        *(float2*)(ob + 8 * DMODEL + 8 * j + fc) =
            make_float2((yr0 * ca - yi0 * sa) * fac, (yr1 * ca - yi1 * sa) * fac);
        *(float2*)(ob + 8 * DMODEL + 8 * j + fc + 32) =
            make_float2((yr0 * sa + yi0 * ca) * fac, (yr1 * sa + yi1 * ca) * fac);
    }
}

// =========================================================================
extern "C" void kernel_launch(void* const* d_in, const int* in_sizes, int n_in,
                              void* d_out, int out_size)
{
    (void)in_sizes; (void)n_in; (void)out_size;

    const float* x    = (const float*)d_in[0];
    const float* Wq   = (const float*)d_in[1];
    const float* Wk   = (const float*)d_in[2];
    const float* Wv   = (const float*)d_in[3];
    const float* We   = (const float*)d_in[4];
    const float* beta = (const float*)d_in[5];
    const float* ivv  = (const float*)d_in[6];
    const float* ovv  = (const float*)d_in[7];
    const float* chi  = (const float*)d_in[8];
    float* out = (float*)d_out;

    float *qp, *kp, *vp, *ap;
    cudaGetSymbolAddress((void**)&qp, g_q);
    cudaGetSymbolAddress((void**)&kp, g_k);
    cudaGetSymbolAddress((void**)&vp, g_v);
    cudaGetSymbolAddress((void**)&ap, g_ao);

    cudaFuncSetAttribute(attn_mma, cudaFuncAttributeMaxDynamicSharedMemorySize,
                         ATTN_SMEM);

    dim3 gqkv(DMODEL / 128, MROWS / 128, 3);   // fused Q/K/V projections
    gemm_f16x2<<<gqkv, 256>>>(x, Wq, Wk, Wv, qp, kp, vp);

    dim3 ga(T_SEQ / 128, NHEADS, BATCH);       // (16, 16, 2)
    attn_mma<<<ga, 256, ATTN_SMEM>>>(qp, kp, vp, beta, ivv, ovv, chi, ap);

    dim3 go(DMODEL / 128, MROWS / 128, 1);     // output projection
    gemm_f16x2<<<go, 256>>>(ap, We, We, We, out, out, out);
}